// round 1
// baseline (speedup 1.0000x reference)
#include <cuda_runtime.h>
#include <math.h>

#define N_NODES 50000
#define N_EDGES 600000
#define C_IN 128
#define C_HID 128
#define C_OUT 64
#define N_GRAPHS 512

// ---------------- scratch (__device__ globals; no allocation allowed) -------
__device__ float g_y[N_NODES * C_HID];     // y = x @ Wl  (reused per layer)
__device__ float g_z[N_NODES * C_HID];     // z = x @ Wr  (reused per layer)
__device__ float g_x1[N_NODES * C_HID];    // relu(layer0)
__device__ float g_x2[N_NODES * C_HID];    // relu(layer1)
__device__ int   g_deg[N_NODES];
__device__ int   g_fill[N_NODES];
__device__ int   g_ptr[N_NODES + 1];
__device__ int   g_csrsrc[N_EDGES];
__device__ int   g_gstart[N_GRAPHS + 1];

// ---------------- helpers ----------------------------------------------------
__global__ void zero_int2(int* a, int na, int* b, int nb) {
    int i = blockIdx.x * blockDim.x + threadIdx.x;
    int stride = gridDim.x * blockDim.x;
    for (int k = i; k < na; k += stride) a[k] = 0;
    for (int k = i; k < nb; k += stride) b[k] = 0;
}

__global__ void hist_kernel(const int* __restrict__ dst, int* __restrict__ deg) {
    int i = blockIdx.x * blockDim.x + threadIdx.x;
    int stride = gridDim.x * blockDim.x;
    for (int e = i; e < N_EDGES; e += stride) atomicAdd(&deg[dst[e]], 1);
}

// single-block exclusive scan over 50000 degrees
__global__ void scan_kernel(const int* __restrict__ deg, int* __restrict__ ptr) {
    __shared__ int sums[1024];
    const int CHUNK = 49;  // 1024*49 = 50176 >= 50000
    int t = threadIdx.x;
    int base = t * CHUNK;
    int s = 0;
    for (int j = 0; j < CHUNK; j++) {
        int i = base + j;
        if (i < N_NODES) s += deg[i];
    }
    sums[t] = s;
    __syncthreads();
    for (int off = 1; off < 1024; off <<= 1) {
        int v = (t >= off) ? sums[t - off] : 0;
        __syncthreads();
        sums[t] += v;
        __syncthreads();
    }
    int run = (t == 0) ? 0 : sums[t - 1];
    for (int j = 0; j < CHUNK; j++) {
        int i = base + j;
        if (i < N_NODES) { ptr[i] = run; run += deg[i]; }
    }
    if (t == 0) ptr[N_NODES] = N_EDGES;
}

__global__ void fill_kernel(const int* __restrict__ src, const int* __restrict__ dst,
                            const int* __restrict__ ptr, int* __restrict__ fill,
                            int* __restrict__ csrsrc) {
    int i = blockIdx.x * blockDim.x + threadIdx.x;
    int stride = gridDim.x * blockDim.x;
    for (int e = i; e < N_EDGES; e += stride) {
        int d = dst[e];
        int pos = ptr[d] + atomicAdd(&fill[d], 1);
        csrsrc[pos] = src[e];
    }
}

// cluster ids sorted ascending -> binary search segment starts
__global__ void gstart_kernel(const int* __restrict__ cluster, int* __restrict__ gstart) {
    int g = blockIdx.x * blockDim.x + threadIdx.x;
    if (g > N_GRAPHS) return;
    if (g == N_GRAPHS) { gstart[g] = N_NODES; return; }
    int lo = 0, hi = N_NODES;  // first idx with cluster[idx] >= g
    while (lo < hi) {
        int mid = (lo + hi) >> 1;
        if (cluster[mid] < g) lo = mid + 1; else hi = mid;
    }
    gstart[g] = lo;
}

// ---------------- SGEMM: C[M,BN] = A[M,128] * B[128,BN] ----------------------
// BM=128, BK=8, 256 threads, thread tile TM=8 x TN (8 or 4)
template <int BN, int TN>
__global__ void sgemm_kernel(const float* __restrict__ A, const float* __restrict__ B,
                             float* __restrict__ C, int M) {
    constexpr int TM = 8;
    __shared__ float As[8][128];
    __shared__ float Bs[8][BN];

    int tid = threadIdx.x;
    int tx = tid & 15;          // 16 in N
    int ty = tid >> 4;          // 16 in M
    int blockRow = blockIdx.x * 128;

    float acc[TM][TN];
#pragma unroll
    for (int i = 0; i < TM; i++)
#pragma unroll
        for (int j = 0; j < TN; j++) acc[i][j] = 0.f;

    int aRow = tid >> 1;
    int aCol = (tid & 1) * 4;
    int gRow = blockRow + aRow;
    bool aValid = (gRow < M);

    for (int k0 = 0; k0 < 128; k0 += 8) {
        // load A tile (transposed into As[k][m])
        float4 av = make_float4(0.f, 0.f, 0.f, 0.f);
        if (aValid) av = *reinterpret_cast<const float4*>(&A[gRow * 128 + k0 + aCol]);
        As[aCol + 0][aRow] = av.x;
        As[aCol + 1][aRow] = av.y;
        As[aCol + 2][aRow] = av.z;
        As[aCol + 3][aRow] = av.w;
        // load B tile
        if (BN == 128) {
            int bRow = tid >> 5;
            int bCol = (tid & 31) * 4;
            *reinterpret_cast<float4*>(&Bs[bRow][bCol]) =
                *reinterpret_cast<const float4*>(&B[(k0 + bRow) * BN + bCol]);
        } else {  // BN == 64
            int bRow = tid >> 5;
            int bCol = (tid & 31) * 2;
            *reinterpret_cast<float2*>(&Bs[bRow][bCol]) =
                *reinterpret_cast<const float2*>(&B[(k0 + bRow) * BN + bCol]);
        }
        __syncthreads();

#pragma unroll
        for (int kk = 0; kk < 8; kk++) {
            float4 a0 = *reinterpret_cast<const float4*>(&As[kk][ty * 8]);
            float4 a1 = *reinterpret_cast<const float4*>(&As[kk][ty * 8 + 4]);
            float am[TM] = {a0.x, a0.y, a0.z, a0.w, a1.x, a1.y, a1.z, a1.w};
            float bn[TN];
            if (TN == 8) {
                float4 b0 = *reinterpret_cast<const float4*>(&Bs[kk][tx * TN]);
                float4 b1 = *reinterpret_cast<const float4*>(&Bs[kk][tx * TN + 4]);
                bn[0] = b0.x; bn[1] = b0.y; bn[2] = b0.z; bn[3] = b0.w;
                bn[4] = b1.x; bn[5] = b1.y; bn[6] = b1.z; bn[7] = b1.w;
            } else {
                float4 b0 = *reinterpret_cast<const float4*>(&Bs[kk][tx * TN]);
                bn[0] = b0.x; bn[1] = b0.y; bn[2] = b0.z; bn[3] = b0.w;
            }
#pragma unroll
            for (int i = 0; i < TM; i++)
#pragma unroll
                for (int j = 0; j < TN; j++) acc[i][j] = fmaf(am[i], bn[j], acc[i][j]);
        }
        __syncthreads();
    }

#pragma unroll
    for (int i = 0; i < TM; i++) {
        int row = blockRow + ty * 8 + i;
        if (row < M) {
            if (TN == 8) {
                *reinterpret_cast<float4*>(&C[row * BN + tx * TN]) =
                    make_float4(acc[i][0], acc[i][1], acc[i][2], acc[i][3]);
                *reinterpret_cast<float4*>(&C[row * BN + tx * TN + 4]) =
                    make_float4(acc[i][4], acc[i][5], acc[i][6], acc[i][7]);
            } else {
                *reinterpret_cast<float4*>(&C[row * BN + tx * TN]) =
                    make_float4(acc[i][0], acc[i][1], acc[i][2], acc[i][3]);
            }
        }
    }
}

// ---------------- aggregation: h = mean_agg(y) + bl + z, 128-ch --------------
// one warp per node, 4 channels per lane (float4)
__global__ void agg128_kernel(const float* __restrict__ y, const float* __restrict__ z,
                              const float* __restrict__ bl,
                              const int* __restrict__ ptr, const int* __restrict__ csrsrc,
                              float* __restrict__ out_relu,       // always written
                              float* __restrict__ out_pre) {      // optional (layer1's "out")
    int warpsPerBlock = blockDim.x >> 5;
    int node = blockIdx.x * warpsPerBlock + (threadIdx.x >> 5);
    if (node >= N_NODES) return;
    int lane = threadIdx.x & 31;

    int lo = ptr[node], hi = ptr[node + 1];
    float4 acc = make_float4(0.f, 0.f, 0.f, 0.f);
#pragma unroll 4
    for (int e = lo; e < hi; e++) {
        int s = csrsrc[e];
        float4 v = *reinterpret_cast<const float4*>(&y[s * 128 + lane * 4]);
        acc.x += v.x; acc.y += v.y; acc.z += v.z; acc.w += v.w;
    }
    float inv = 1.f / (float)max(hi - lo, 1);
    float4 b = *reinterpret_cast<const float4*>(&bl[lane * 4]);
    float4 zi = *reinterpret_cast<const float4*>(&z[node * 128 + lane * 4]);
    float4 h;
    h.x = acc.x * inv + b.x + zi.x;
    h.y = acc.y * inv + b.y + zi.y;
    h.z = acc.z * inv + b.z + zi.z;
    h.w = acc.w * inv + b.w + zi.w;
    if (out_pre) *reinterpret_cast<float4*>(&out_pre[node * 128 + lane * 4]) = h;
    float4 r = make_float4(fmaxf(h.x, 0.f), fmaxf(h.y, 0.f), fmaxf(h.z, 0.f), fmaxf(h.w, 0.f));
    *reinterpret_cast<float4*>(&out_relu[node * 128 + lane * 4]) = r;
}

// ---------------- final aggregation (64-ch) + log_softmax --------------------
__global__ void agg64_lsm_kernel(const float* __restrict__ y, const float* __restrict__ z,
                                 const float* __restrict__ bl,
                                 const int* __restrict__ ptr, const int* __restrict__ csrsrc,
                                 float* __restrict__ out) {
    int warpsPerBlock = blockDim.x >> 5;
    int node = blockIdx.x * warpsPerBlock + (threadIdx.x >> 5);
    if (node >= N_NODES) return;
    int lane = threadIdx.x & 31;

    int lo = ptr[node], hi = ptr[node + 1];
    float2 acc = make_float2(0.f, 0.f);
#pragma unroll 4
    for (int e = lo; e < hi; e++) {
        int s = csrsrc[e];
        float2 v = *reinterpret_cast<const float2*>(&y[s * 64 + lane * 2]);
        acc.x += v.x; acc.y += v.y;
    }
    float inv = 1.f / (float)max(hi - lo, 1);
    float2 b = *reinterpret_cast<const float2*>(&bl[lane * 2]);
    float2 zi = *reinterpret_cast<const float2*>(&z[node * 64 + lane * 2]);
    float2 h;
    h.x = acc.x * inv + b.x + zi.x;
    h.y = acc.y * inv + b.y + zi.y;

    // warp-level log_softmax over 64 values (2 per lane)
    float m = fmaxf(h.x, h.y);
#pragma unroll
    for (int off = 16; off > 0; off >>= 1)
        m = fmaxf(m, __shfl_xor_sync(0xFFFFFFFFu, m, off));
    float s = expf(h.x - m) + expf(h.y - m);
#pragma unroll
    for (int off = 16; off > 0; off >>= 1)
        s += __shfl_xor_sync(0xFFFFFFFFu, s, off);
    float ls = logf(s);
    float2 r = make_float2(h.x - m - ls, h.y - m - ls);
    *reinterpret_cast<float2*>(&out[node * 64 + lane * 2]) = r;
}

// ---------------- pooling: warp per graph (sorted clusters) ------------------
__global__ void pool_kernel(const float* __restrict__ x, const int* __restrict__ gstart,
                            float* __restrict__ gout) {
    int warpsPerBlock = blockDim.x >> 5;
    int g = blockIdx.x * warpsPerBlock + (threadIdx.x >> 5);
    if (g >= N_GRAPHS) return;
    int lane = threadIdx.x & 31;
    int lo = gstart[g], hi = gstart[g + 1];
    float4 acc = make_float4(0.f, 0.f, 0.f, 0.f);
    for (int i = lo; i < hi; i++) {
        float4 v = *reinterpret_cast<const float4*>(&x[i * 128 + lane * 4]);
        acc.x += v.x; acc.y += v.y; acc.z += v.z; acc.w += v.w;
    }
    float inv = 1.f / (float)max(hi - lo, 1);
    acc.x *= inv; acc.y *= inv; acc.z *= inv; acc.w *= inv;
    *reinterpret_cast<float4*>(&gout[g * 128 + lane * 4]) = acc;
}

// ---------------- launch -----------------------------------------------------
extern "C" void kernel_launch(void* const* d_in, const int* in_sizes, int n_in,
                              void* d_out, int out_size) {
    const float* x       = (const float*)d_in[0];
    const int*   ei      = (const int*)d_in[1];
    const int*   cluster = (const int*)d_in[2];
    const float* Wl0 = (const float*)d_in[3];
    const float* bl0 = (const float*)d_in[4];
    const float* Wr0 = (const float*)d_in[5];
    const float* Wl1 = (const float*)d_in[6];
    const float* bl1 = (const float*)d_in[7];
    const float* Wr1 = (const float*)d_in[8];
    const float* Wl2 = (const float*)d_in[9];
    const float* bl2 = (const float*)d_in[10];
    const float* Wr2 = (const float*)d_in[11];

    const int* src = ei;
    const int* dst = ei + N_EDGES;

    float* out = (float*)d_out;
    float* out_lsm = out;                                // [50000, 64]
    float* out_pre = out + N_NODES * C_OUT;              // [50000, 128]
    float* out_g   = out + N_NODES * C_OUT + N_NODES * C_HID;  // [512, 128]

    float *y, *z, *x1, *x2;
    int *deg, *fill, *ptr, *csrsrc, *gstart;
    cudaGetSymbolAddress((void**)&y, g_y);
    cudaGetSymbolAddress((void**)&z, g_z);
    cudaGetSymbolAddress((void**)&x1, g_x1);
    cudaGetSymbolAddress((void**)&x2, g_x2);
    cudaGetSymbolAddress((void**)&deg, g_deg);
    cudaGetSymbolAddress((void**)&fill, g_fill);
    cudaGetSymbolAddress((void**)&ptr, g_ptr);
    cudaGetSymbolAddress((void**)&csrsrc, g_csrsrc);
    cudaGetSymbolAddress((void**)&gstart, g_gstart);

    // ---- CSR build (once; edges static across layers) ----
    zero_int2<<<128, 256>>>(deg, N_NODES, fill, N_NODES);
    hist_kernel<<<592, 256>>>(dst, deg);
    scan_kernel<<<1, 1024>>>(deg, ptr);
    fill_kernel<<<592, 256>>>(src, dst, ptr, fill, csrsrc);
    gstart_kernel<<<3, 256>>>(cluster, gstart);

    const int GEMM_GRID = (N_NODES + 127) / 128;  // 391
    const int AGG_BLOCKS = (N_NODES + 7) / 8;     // warp per node, 8 warps/block

    // ---- layer 0 ----
    sgemm_kernel<128, 8><<<GEMM_GRID, 256>>>(x, Wl0, y, N_NODES);
    sgemm_kernel<128, 8><<<GEMM_GRID, 256>>>(x, Wr0, z, N_NODES);
    agg128_kernel<<<AGG_BLOCKS, 256>>>(y, z, bl0, ptr, csrsrc, x1, nullptr);

    // ---- layer 1 (writes pre-relu "out" + relu x2) ----
    sgemm_kernel<128, 8><<<GEMM_GRID, 256>>>(x1, Wl1, y, N_NODES);
    sgemm_kernel<128, 8><<<GEMM_GRID, 256>>>(x1, Wr1, z, N_NODES);
    agg128_kernel<<<AGG_BLOCKS, 256>>>(y, z, bl1, ptr, csrsrc, x2, out_pre);

    // ---- pooling over sorted clusters ----
    pool_kernel<<<(N_GRAPHS + 7) / 8, 256>>>(x2, gstart, out_g);

    // ---- layer 2 + log_softmax ----
    sgemm_kernel<64, 4><<<GEMM_GRID, 256>>>(x2, Wl2, y, N_NODES);
    sgemm_kernel<64, 4><<<GEMM_GRID, 256>>>(x2, Wr2, z, N_NODES);
    agg64_lsm_kernel<<<AGG_BLOCKS, 256>>>(y, z, bl2, ptr, csrsrc, out_lsm);
}

// round 2
// speedup vs baseline: 1.1132x; 1.1132x over previous
#include <cuda_runtime.h>
#include <math.h>

#define N_NODES 50000
#define N_EDGES 600000
#define C_IN 128
#define C_HID 128
#define C_OUT 64
#define N_GRAPHS 512

// ---------------- scratch (__device__ globals; no allocation allowed) -------
__device__ float g_y[N_NODES * C_HID];     // y = x @ Wl  (reused per layer)
__device__ float g_z[N_NODES * C_HID];     // z = x @ Wr  (reused per layer)
__device__ float g_x1[N_NODES * C_HID];    // relu(layer0)
__device__ float g_x2[N_NODES * C_HID];    // relu(layer1)
__device__ int   g_deg[N_NODES];
__device__ int   g_fill[N_NODES];
__device__ int   g_ptr[N_NODES + 1];
__device__ int   g_csrsrc[N_EDGES];
__device__ int   g_gstart[N_GRAPHS + 1];

// ---------------- helpers ----------------------------------------------------
__global__ void zero_int2(int* a, int na, int* b, int nb) {
    int i = blockIdx.x * blockDim.x + threadIdx.x;
    int stride = gridDim.x * blockDim.x;
    for (int k = i; k < na; k += stride) a[k] = 0;
    for (int k = i; k < nb; k += stride) b[k] = 0;
}

__global__ void hist_kernel(const int* __restrict__ dst, int* __restrict__ deg) {
    int i = blockIdx.x * blockDim.x + threadIdx.x;
    int stride = gridDim.x * blockDim.x;
    for (int e = i; e < N_EDGES; e += stride) atomicAdd(&deg[dst[e]], 1);
}

// single-block exclusive scan over 50000 degrees
__global__ void scan_kernel(const int* __restrict__ deg, int* __restrict__ ptr) {
    __shared__ int sums[1024];
    const int CHUNK = 49;
    int t = threadIdx.x;
    int base = t * CHUNK;
    int s = 0;
    for (int j = 0; j < CHUNK; j++) {
        int i = base + j;
        if (i < N_NODES) s += deg[i];
    }
    sums[t] = s;
    __syncthreads();
    for (int off = 1; off < 1024; off <<= 1) {
        int v = (t >= off) ? sums[t - off] : 0;
        __syncthreads();
        sums[t] += v;
        __syncthreads();
    }
    int run = (t == 0) ? 0 : sums[t - 1];
    for (int j = 0; j < CHUNK; j++) {
        int i = base + j;
        if (i < N_NODES) { ptr[i] = run; run += deg[i]; }
    }
    if (t == 0) ptr[N_NODES] = N_EDGES;
}

__global__ void fill_kernel(const int* __restrict__ src, const int* __restrict__ dst,
                            const int* __restrict__ ptr, int* __restrict__ fill,
                            int* __restrict__ csrsrc) {
    int i = blockIdx.x * blockDim.x + threadIdx.x;
    int stride = gridDim.x * blockDim.x;
    for (int e = i; e < N_EDGES; e += stride) {
        int d = dst[e];
        int pos = ptr[d] + atomicAdd(&fill[d], 1);
        csrsrc[pos] = src[e];
    }
}

__global__ void gstart_kernel(const int* __restrict__ cluster, int* __restrict__ gstart) {
    int g = blockIdx.x * blockDim.x + threadIdx.x;
    if (g > N_GRAPHS) return;
    if (g == N_GRAPHS) { gstart[g] = N_NODES; return; }
    int lo = 0, hi = N_NODES;
    while (lo < hi) {
        int mid = (lo + hi) >> 1;
        if (cluster[mid] < g) lo = mid + 1; else hi = mid;
    }
    gstart[g] = lo;
}

// ---------------- 3xTF32 tensor-core GEMM ------------------------------------
// C[M,BN] = A[M,128] @ B[128,BN], fp32 in/out, 3xTF32 decomposition.
// Fused pair: blockIdx.y selects (B0->C0) or (B1->C1). BM=128, BK=16.
// 8 warps as 2(m) x 4(n); warp tile 64 x (8*WNT). Fragment-packed SMEM.

__device__ __forceinline__ unsigned f2tf32(float x) {
    unsigned u;
    asm("cvt.rna.tf32.f32 %0, %1;" : "=r"(u) : "f"(x));
    return u;
}

#define MMA_TF32(c, a, b)                                                          \
    asm volatile(                                                                  \
        "mma.sync.aligned.m16n8k8.row.col.f32.tf32.tf32.f32 "                      \
        "{%0,%1,%2,%3},{%4,%5,%6,%7},{%8,%9},{%0,%1,%2,%3};"                       \
        : "+f"(c[0]), "+f"(c[1]), "+f"(c[2]), "+f"(c[3])                           \
        : "r"(a[0]), "r"(a[1]), "r"(a[2]), "r"(a[3]), "r"(b[0]), "r"(b[1]))

template <int BN>
__global__ __launch_bounds__(256) void mma_gemm(const float* __restrict__ A,
                                                const float* __restrict__ B0,
                                                const float* __restrict__ B1,
                                                float* __restrict__ C0,
                                                float* __restrict__ C1, int M) {
    constexpr int WNT = (BN == 128) ? 4 : 2;       // n8-tiles per warp
    constexpr int NT_BLK = BN / 8;                 // n8-tiles per block
    constexpr int BSLOT = (BN == 128) ? 4 : 2;     // B fill slots per thread

    const float* B = blockIdx.y ? B1 : B0;
    float* C = blockIdx.y ? C1 : C0;

    __shared__ float As_h[2][8][32][4];
    __shared__ float As_l[2][8][32][4];
    __shared__ float Bs_h[2][NT_BLK][32][2];
    __shared__ float Bs_l[2][NT_BLK][32][2];

    int tid = threadIdx.x;
    int lane = tid & 31;
    int warp = tid >> 5;
    int wm = warp & 1;        // warp m index (0..1) -> rows wm*64
    int wn = warp >> 1;       // warp n index (0..3)
    int bRow = blockIdx.x * 128;

    float acc[4][WNT][4];
#pragma unroll
    for (int mt = 0; mt < 4; mt++)
#pragma unroll
        for (int nt = 0; nt < WNT; nt++)
#pragma unroll
            for (int j = 0; j < 4; j++) acc[mt][nt][j] = 0.f;

    float a_pre[8];
    float b_pre[BSLOT * 2];

    // ---- register prefetch of one k-tile (k0..k0+15) ----
    auto loadA = [&](int k0) {
#pragma unroll
        for (int i = 0; i < 2; i++) {
            int s = tid + i * 256;
            int kt = s >> 8, mt = (s >> 5) & 7, ln = s & 31;
            int m = bRow + mt * 16 + (ln >> 2);
            int kk = k0 + kt * 8 + (ln & 3);
#pragma unroll
            for (int j = 0; j < 4; j++) {
                int mm = m + 8 * (j & 1);
                int kc = kk + 4 * (j >> 1);
                a_pre[i * 4 + j] = (mm < M) ? A[mm * 128 + kc] : 0.f;
            }
        }
    };
    auto loadB = [&](int k0) {
#pragma unroll
        for (int i = 0; i < BSLOT; i++) {
            int s = tid + i * 256;
            int kt, nt, ln;
            if (BN == 128) { kt = s >> 9; nt = (s >> 5) & 15; ln = s & 31; }
            else           { kt = s >> 8; nt = (s >> 5) & 7;  ln = s & 31; }
            int n = nt * 8 + (ln >> 2);
            int kk = k0 + kt * 8 + (ln & 3);
#pragma unroll
            for (int j = 0; j < 2; j++) {
                b_pre[i * 2 + j] = B[(kk + 4 * j) * BN + n];
            }
        }
    };
    auto storeAB = [&]() {
#pragma unroll
        for (int i = 0; i < 2; i++) {
            int s = tid + i * 256;
            int kt = s >> 8, mt = (s >> 5) & 7, ln = s & 31;
#pragma unroll
            for (int j = 0; j < 4; j++) {
                float x = a_pre[i * 4 + j];
                unsigned h = f2tf32(x);
                float hf = __uint_as_float(h);
                unsigned l = f2tf32(x - hf);
                As_h[kt][mt][ln][j] = hf;
                As_l[kt][mt][ln][j] = __uint_as_float(l);
            }
        }
#pragma unroll
        for (int i = 0; i < BSLOT; i++) {
            int s = tid + i * 256;
            int kt, nt, ln;
            if (BN == 128) { kt = s >> 9; nt = (s >> 5) & 15; ln = s & 31; }
            else           { kt = s >> 8; nt = (s >> 5) & 7;  ln = s & 31; }
#pragma unroll
            for (int j = 0; j < 2; j++) {
                float x = b_pre[i * 2 + j];
                unsigned h = f2tf32(x);
                float hf = __uint_as_float(h);
                unsigned l = f2tf32(x - hf);
                Bs_h[kt][nt][ln][j] = hf;
                Bs_l[kt][nt][ln][j] = __uint_as_float(l);
            }
        }
    };

    loadA(0);
    loadB(0);

    for (int it = 0; it < 8; it++) {
        storeAB();
        __syncthreads();
        if (it < 7) { loadA((it + 1) * 16); loadB((it + 1) * 16); }

#pragma unroll
        for (int ks = 0; ks < 2; ks++) {
            unsigned ah[4][4], al[4][4];
#pragma unroll
            for (int mt = 0; mt < 4; mt++) {
                int mg = wm * 4 + mt;
                float4 h4 = *reinterpret_cast<const float4*>(&As_h[ks][mg][lane][0]);
                float4 l4 = *reinterpret_cast<const float4*>(&As_l[ks][mg][lane][0]);
                ah[mt][0] = __float_as_uint(h4.x); ah[mt][1] = __float_as_uint(h4.y);
                ah[mt][2] = __float_as_uint(h4.z); ah[mt][3] = __float_as_uint(h4.w);
                al[mt][0] = __float_as_uint(l4.x); al[mt][1] = __float_as_uint(l4.y);
                al[mt][2] = __float_as_uint(l4.z); al[mt][3] = __float_as_uint(l4.w);
            }
            unsigned bh[WNT][2], bl[WNT][2];
#pragma unroll
            for (int nt = 0; nt < WNT; nt++) {
                int ng = wn * WNT + nt;
                float2 h2 = *reinterpret_cast<const float2*>(&Bs_h[ks][ng][lane][0]);
                float2 l2 = *reinterpret_cast<const float2*>(&Bs_l[ks][ng][lane][0]);
                bh[nt][0] = __float_as_uint(h2.x); bh[nt][1] = __float_as_uint(h2.y);
                bl[nt][0] = __float_as_uint(l2.x); bl[nt][1] = __float_as_uint(l2.y);
            }
#pragma unroll
            for (int mt = 0; mt < 4; mt++)
#pragma unroll
                for (int nt = 0; nt < WNT; nt++) {
                    MMA_TF32(acc[mt][nt], ah[mt], bh[nt]);
                    MMA_TF32(acc[mt][nt], ah[mt], bl[nt]);
                    MMA_TF32(acc[mt][nt], al[mt], bh[nt]);
                }
        }
        __syncthreads();
    }

    // ---- epilogue ----
#pragma unroll
    for (int mt = 0; mt < 4; mt++) {
        int row = bRow + wm * 64 + mt * 16 + (lane >> 2);
#pragma unroll
        for (int nt = 0; nt < WNT; nt++) {
            int col = wn * (8 * WNT) + nt * 8 + (lane & 3) * 2;
            if (row < M)
                *reinterpret_cast<float2*>(&C[row * BN + col]) =
                    make_float2(acc[mt][nt][0], acc[mt][nt][1]);
            if (row + 8 < M)
                *reinterpret_cast<float2*>(&C[(row + 8) * BN + col]) =
                    make_float2(acc[mt][nt][2], acc[mt][nt][3]);
        }
    }
}

// ---------------- aggregation: h = mean_agg(y) + bl + z, 128-ch --------------
__global__ void agg128_kernel(const float* __restrict__ y, const float* __restrict__ z,
                              const float* __restrict__ bl,
                              const int* __restrict__ ptr, const int* __restrict__ csrsrc,
                              float* __restrict__ out_relu,
                              float* __restrict__ out_pre) {
    int warpsPerBlock = blockDim.x >> 5;
    int node = blockIdx.x * warpsPerBlock + (threadIdx.x >> 5);
    if (node >= N_NODES) return;
    int lane = threadIdx.x & 31;

    int lo = ptr[node], hi = ptr[node + 1];
    float4 acc = make_float4(0.f, 0.f, 0.f, 0.f);
#pragma unroll 4
    for (int e = lo; e < hi; e++) {
        int s = csrsrc[e];
        float4 v = *reinterpret_cast<const float4*>(&y[s * 128 + lane * 4]);
        acc.x += v.x; acc.y += v.y; acc.z += v.z; acc.w += v.w;
    }
    float inv = 1.f / (float)max(hi - lo, 1);
    float4 b = *reinterpret_cast<const float4*>(&bl[lane * 4]);
    float4 zi = *reinterpret_cast<const float4*>(&z[node * 128 + lane * 4]);
    float4 h;
    h.x = acc.x * inv + b.x + zi.x;
    h.y = acc.y * inv + b.y + zi.y;
    h.z = acc.z * inv + b.z + zi.z;
    h.w = acc.w * inv + b.w + zi.w;
    if (out_pre) *reinterpret_cast<float4*>(&out_pre[node * 128 + lane * 4]) = h;
    float4 r = make_float4(fmaxf(h.x, 0.f), fmaxf(h.y, 0.f), fmaxf(h.z, 0.f), fmaxf(h.w, 0.f));
    *reinterpret_cast<float4*>(&out_relu[node * 128 + lane * 4]) = r;
}

// ---------------- final aggregation (64-ch) + log_softmax --------------------
__global__ void agg64_lsm_kernel(const float* __restrict__ y, const float* __restrict__ z,
                                 const float* __restrict__ bl,
                                 const int* __restrict__ ptr, const int* __restrict__ csrsrc,
                                 float* __restrict__ out) {
    int warpsPerBlock = blockDim.x >> 5;
    int node = blockIdx.x * warpsPerBlock + (threadIdx.x >> 5);
    if (node >= N_NODES) return;
    int lane = threadIdx.x & 31;

    int lo = ptr[node], hi = ptr[node + 1];
    float2 acc = make_float2(0.f, 0.f);
#pragma unroll 4
    for (int e = lo; e < hi; e++) {
        int s = csrsrc[e];
        float2 v = *reinterpret_cast<const float2*>(&y[s * 64 + lane * 2]);
        acc.x += v.x; acc.y += v.y;
    }
    float inv = 1.f / (float)max(hi - lo, 1);
    float2 b = *reinterpret_cast<const float2*>(&bl[lane * 2]);
    float2 zi = *reinterpret_cast<const float2*>(&z[node * 64 + lane * 2]);
    float2 h;
    h.x = acc.x * inv + b.x + zi.x;
    h.y = acc.y * inv + b.y + zi.y;

    float m = fmaxf(h.x, h.y);
#pragma unroll
    for (int off = 16; off > 0; off >>= 1)
        m = fmaxf(m, __shfl_xor_sync(0xFFFFFFFFu, m, off));
    float s = expf(h.x - m) + expf(h.y - m);
#pragma unroll
    for (int off = 16; off > 0; off >>= 1)
        s += __shfl_xor_sync(0xFFFFFFFFu, s, off);
    float ls = logf(s);
    float2 r = make_float2(h.x - m - ls, h.y - m - ls);
    *reinterpret_cast<float2*>(&out[node * 64 + lane * 2]) = r;
}

// ---------------- pooling: warp per graph (sorted clusters) ------------------
__global__ void pool_kernel(const float* __restrict__ x, const int* __restrict__ gstart,
                            float* __restrict__ gout) {
    int warpsPerBlock = blockDim.x >> 5;
    int g = blockIdx.x * warpsPerBlock + (threadIdx.x >> 5);
    if (g >= N_GRAPHS) return;
    int lane = threadIdx.x & 31;
    int lo = gstart[g], hi = gstart[g + 1];
    float4 acc = make_float4(0.f, 0.f, 0.f, 0.f);
    for (int i = lo; i < hi; i++) {
        float4 v = *reinterpret_cast<const float4*>(&x[i * 128 + lane * 4]);
        acc.x += v.x; acc.y += v.y; acc.z += v.z; acc.w += v.w;
    }
    float inv = 1.f / (float)max(hi - lo, 1);
    acc.x *= inv; acc.y *= inv; acc.z *= inv; acc.w *= inv;
    *reinterpret_cast<float4*>(&gout[g * 128 + lane * 4]) = acc;
}

// ---------------- launch -----------------------------------------------------
extern "C" void kernel_launch(void* const* d_in, const int* in_sizes, int n_in,
                              void* d_out, int out_size) {
    const float* x       = (const float*)d_in[0];
    const int*   ei      = (const int*)d_in[1];
    const int*   cluster = (const int*)d_in[2];
    const float* Wl0 = (const float*)d_in[3];
    const float* bl0 = (const float*)d_in[4];
    const float* Wr0 = (const float*)d_in[5];
    const float* Wl1 = (const float*)d_in[6];
    const float* bl1 = (const float*)d_in[7];
    const float* Wr1 = (const float*)d_in[8];
    const float* Wl2 = (const float*)d_in[9];
    const float* bl2 = (const float*)d_in[10];
    const float* Wr2 = (const float*)d_in[11];

    const int* src = ei;
    const int* dst = ei + N_EDGES;

    float* out = (float*)d_out;
    float* out_lsm = out;
    float* out_pre = out + N_NODES * C_OUT;
    float* out_g   = out + N_NODES * C_OUT + N_NODES * C_HID;

    float *y, *z, *x1, *x2;
    int *deg, *fill, *ptr, *csrsrc, *gstart;
    cudaGetSymbolAddress((void**)&y, g_y);
    cudaGetSymbolAddress((void**)&z, g_z);
    cudaGetSymbolAddress((void**)&x1, g_x1);
    cudaGetSymbolAddress((void**)&x2, g_x2);
    cudaGetSymbolAddress((void**)&deg, g_deg);
    cudaGetSymbolAddress((void**)&fill, g_fill);
    cudaGetSymbolAddress((void**)&ptr, g_ptr);
    cudaGetSymbolAddress((void**)&csrsrc, g_csrsrc);
    cudaGetSymbolAddress((void**)&gstart, g_gstart);

    // ---- CSR build (edges static across layers) ----
    zero_int2<<<128, 256>>>(deg, N_NODES, fill, N_NODES);
    hist_kernel<<<592, 256>>>(dst, deg);
    scan_kernel<<<1, 1024>>>(deg, ptr);
    fill_kernel<<<592, 256>>>(src, dst, ptr, fill, csrsrc);
    gstart_kernel<<<3, 256>>>(cluster, gstart);

    const int GEMM_GRID = (N_NODES + 127) / 128;  // 391
    const int AGG_BLOCKS = (N_NODES + 7) / 8;
    dim3 gpair(GEMM_GRID, 2);

    // ---- layer 0 ----
    mma_gemm<128><<<gpair, 256>>>(x, Wl0, Wr0, y, z, N_NODES);
    agg128_kernel<<<AGG_BLOCKS, 256>>>(y, z, bl0, ptr, csrsrc, x1, nullptr);

    // ---- layer 1 (writes pre-relu "out" + relu x2) ----
    mma_gemm<128><<<gpair, 256>>>(x1, Wl1, Wr1, y, z, N_NODES);
    agg128_kernel<<<AGG_BLOCKS, 256>>>(y, z, bl1, ptr, csrsrc, x2, out_pre);

    // ---- pooling over sorted clusters ----
    pool_kernel<<<(N_GRAPHS + 7) / 8, 256>>>(x2, gstart, out_g);

    // ---- layer 2 + log_softmax ----
    mma_gemm<64><<<gpair, 256>>>(x2, Wl2, Wr2, y, z, N_NODES);
    agg64_lsm_kernel<<<AGG_BLOCKS, 256>>>(y, z, bl2, ptr, csrsrc, out_lsm);
}

// round 4
// speedup vs baseline: 1.6250x; 1.4597x over previous
#include <cuda_runtime.h>
#include <cuda_bf16.h>
#include <math.h>
#include <stdint.h>

#define N_NODES 50000
#define N_EDGES 600000
#define C_HID 128
#define C_OUT 64
#define N_GRAPHS 512
#define MT_PAD 3128   // 391*8 m-tiles of 16 rows (>= ceil(50000/16)=3125)

// ---------------- scratch (__device__ globals) -------------------------------
__device__ float    g_y[N_NODES * C_HID];
__device__ float    g_z[N_NODES * C_HID];
__device__ float    g_x1[N_NODES * C_HID];
__device__ float    g_x2[N_NODES * C_HID];
__device__ uint32_t g_ah[MT_PAD * 8 * 128];   // A hi, fragment-packed bf16x2
__device__ uint32_t g_al[MT_PAD * 8 * 128];   // A lo
__device__ uint32_t g_wh[6 * 8192];           // 6 weights hi, fragment-packed
__device__ uint32_t g_wl[6 * 8192];           // 6 weights lo
__device__ int      g_deg[N_NODES];
__device__ int      g_fill[N_NODES];
__device__ int      g_ptr[N_NODES + 1];
__device__ int      g_csrsrc[N_EDGES];
__device__ int      g_gstart[N_GRAPHS + 1];

// ---------------- CSR / misc helpers -----------------------------------------
__global__ void zero_int2(int* a, int na, int* b, int nb) {
    int i = blockIdx.x * blockDim.x + threadIdx.x;
    int stride = gridDim.x * blockDim.x;
    for (int k = i; k < na; k += stride) a[k] = 0;
    for (int k = i; k < nb; k += stride) b[k] = 0;
}

__global__ void hist_kernel(const int* __restrict__ dst, int* __restrict__ deg) {
    int i = blockIdx.x * blockDim.x + threadIdx.x;
    int stride = gridDim.x * blockDim.x;
    for (int e = i; e < N_EDGES; e += stride) atomicAdd(&deg[dst[e]], 1);
}

__global__ void scan_kernel(const int* __restrict__ deg, int* __restrict__ ptr) {
    __shared__ int sums[1024];
    const int CHUNK = 49;
    int t = threadIdx.x;
    int base = t * CHUNK;
    int s = 0;
    for (int j = 0; j < CHUNK; j++) {
        int i = base + j;
        if (i < N_NODES) s += deg[i];
    }
    sums[t] = s;
    __syncthreads();
    for (int off = 1; off < 1024; off <<= 1) {
        int v = (t >= off) ? sums[t - off] : 0;
        __syncthreads();
        sums[t] += v;
        __syncthreads();
    }
    int run = (t == 0) ? 0 : sums[t - 1];
    for (int j = 0; j < CHUNK; j++) {
        int i = base + j;
        if (i < N_NODES) { ptr[i] = run; run += deg[i]; }
    }
    if (t == 0) ptr[N_NODES] = N_EDGES;
}

__global__ void fill_kernel(const int* __restrict__ src, const int* __restrict__ dst,
                            const int* __restrict__ ptr, int* __restrict__ fill,
                            int* __restrict__ csrsrc) {
    int i = blockIdx.x * blockDim.x + threadIdx.x;
    int stride = gridDim.x * blockDim.x;
    for (int e = i; e < N_EDGES; e += stride) {
        int d = dst[e];
        int pos = ptr[d] + atomicAdd(&fill[d], 1);
        csrsrc[pos] = src[e];
    }
}

__global__ void gstart_kernel(const int* __restrict__ cluster, int* __restrict__ gstart) {
    int g = blockIdx.x * blockDim.x + threadIdx.x;
    if (g > N_GRAPHS) return;
    if (g == N_GRAPHS) { gstart[g] = N_NODES; return; }
    int lo = 0, hi = N_NODES;
    while (lo < hi) {
        int mid = (lo + hi) >> 1;
        if (cluster[mid] < g) lo = mid + 1; else hi = mid;
    }
    gstart[g] = lo;
}

// ---------------- bf16 split/pack helpers ------------------------------------
__device__ __forceinline__ uint32_t pack_split(float x, float y, uint32_t& lo) {
    __nv_bfloat16 hx = __float2bfloat16(x);
    __nv_bfloat16 hy = __float2bfloat16(y);
    float rx = x - __bfloat162float(hx);
    float ry = y - __bfloat162float(hy);
    __nv_bfloat16 lx = __float2bfloat16(rx);
    __nv_bfloat16 ly = __float2bfloat16(ry);
    uint16_t bhx = *reinterpret_cast<uint16_t*>(&hx);
    uint16_t bhy = *reinterpret_cast<uint16_t*>(&hy);
    uint16_t blx = *reinterpret_cast<uint16_t*>(&lx);
    uint16_t bly = *reinterpret_cast<uint16_t*>(&ly);
    lo = ((uint32_t)bly << 16) | blx;
    return ((uint32_t)bhy << 16) | bhx;
}

// ---- pack A [M,128] f32 -> fragment-packed hi/lo bf16x2 tiles ---------------
// tile (mt, kt): 16x16 block. lane holds regs a0..a3 (mma m16n8k16 A layout).
__global__ void pack_a(const float* __restrict__ A, uint32_t* __restrict__ Ah,
                       uint32_t* __restrict__ Al, int M) {
    int tile = blockIdx.x * 8 + (threadIdx.x >> 5);
    if (tile >= MT_PAD * 8) return;
    int mt = tile >> 3, kt = tile & 7;
    int lane = threadIdx.x & 31, gid = lane >> 2, tig = lane & 3;
    uint32_t h[4], l[4];
#pragma unroll
    for (int r = 0; r < 4; r++) {
        int row = mt * 16 + gid + (r & 1) * 8;
        int col = kt * 16 + tig * 2 + (r >> 1) * 8;
        float2 v = make_float2(0.f, 0.f);
        if (row < M) v = *reinterpret_cast<const float2*>(&A[row * 128 + col]);
        h[r] = pack_split(v.x, v.y, l[r]);
    }
    *reinterpret_cast<uint4*>(&Ah[(tile * 32 + lane) * 4]) = make_uint4(h[0], h[1], h[2], h[3]);
    *reinterpret_cast<uint4*>(&Al[(tile * 32 + lane) * 4]) = make_uint4(l[0], l[1], l[2], l[3]);
}

// ---- pack 6 weight matrices -> fragment-packed hi/lo (B layout, col-major) --
__global__ void pack_w6(const float* W0, const float* W1, const float* W2,
                        const float* W3, const float* W4, const float* W5,
                        uint32_t* __restrict__ Wh, uint32_t* __restrict__ Wl) {
    int mat = blockIdx.y;
    const float* W;
    int BN;
    switch (mat) {
        case 0: W = W0; BN = 128; break;
        case 1: W = W1; BN = 128; break;
        case 2: W = W2; BN = 128; break;
        case 3: W = W3; BN = 128; break;
        case 4: W = W4; BN = 64; break;
        default: W = W5; BN = 64; break;
    }
    int NT = BN / 8;
    int tile = blockIdx.x * 8 + (threadIdx.x >> 5);
    if (tile >= 8 * NT) return;
    int kt = tile / NT, nt = tile % NT;
    int lane = threadIdx.x & 31, gid = lane >> 2, tig = lane & 3;
    int col = nt * 8 + gid;
    uint32_t h[2], l[2];
#pragma unroll
    for (int r = 0; r < 2; r++) {
        int k = kt * 16 + tig * 2 + r * 8;
        float v0 = W[k * BN + col];
        float v1 = W[(k + 1) * BN + col];
        h[r] = pack_split(v0, v1, l[r]);
    }
    *reinterpret_cast<uint2*>(&Wh[mat * 8192 + (tile * 32 + lane) * 2]) = make_uint2(h[0], h[1]);
    *reinterpret_cast<uint2*>(&Wl[mat * 8192 + (tile * 32 + lane) * 2]) = make_uint2(l[0], l[1]);
}

// ---------------- bf16 split GEMM --------------------------------------------
__device__ __forceinline__ uint32_t smem_u32(const void* p) {
    uint32_t a;
    asm("{ .reg .u64 t; cvta.to.shared.u64 t, %1; cvt.u32.u64 %0, t; }" : "=r"(a) : "l"(p));
    return a;
}

__device__ __forceinline__ void cp16(uint32_t dst, const void* src) {
    asm volatile("cp.async.cg.shared.global [%0], [%1], 16;" :: "r"(dst), "l"(src) : "memory");
}

#define MMA_BF16(c, a, b)                                                         \
    asm volatile(                                                                 \
        "mma.sync.aligned.m16n8k16.row.col.f32.bf16.bf16.f32 "                    \
        "{%0,%1,%2,%3},{%4,%5,%6,%7},{%8,%9},{%0,%1,%2,%3};"                      \
        : "+f"(c[0]), "+f"(c[1]), "+f"(c[2]), "+f"(c[3])                          \
        : "r"(a[0]), "r"(a[1]), "r"(a[2]), "r"(a[3]), "r"(b[0]), "r"(b[1]))

// C[M,BN] = A[M,128] @ W[128,BN] (3-term bf16 split, fp32 accumulate).
// blockIdx.y selects (W,C) pair. BM=128, BK=32, 2-stage cp.async pipeline.
template <int BN>
__global__ __launch_bounds__(256, 2) void bf16_gemm(
    const uint32_t* __restrict__ Ah, const uint32_t* __restrict__ Al,
    const uint32_t* __restrict__ Bh0, const uint32_t* __restrict__ Bl0,
    const uint32_t* __restrict__ Bh1, const uint32_t* __restrict__ Bl1,
    float* __restrict__ C0, float* __restrict__ C1, int M) {
    constexpr int NT = BN / 8;
    constexpr int WNT = NT / 4;
    constexpr int STAGE = 16384 + NT * 1024;
    extern __shared__ char smem[];

    const uint32_t* Bh = blockIdx.y ? Bh1 : Bh0;
    const uint32_t* Bl = blockIdx.y ? Bl1 : Bl0;
    float* C = blockIdx.y ? C1 : C0;

    uint32_t sb = smem_u32(smem);
    int tid = threadIdx.x, lane = tid & 31, warp = tid >> 5;
    int wm = warp & 1, wn = warp >> 1;
    int bRow = blockIdx.x * 128;

    float acc[4][WNT][4];
#pragma unroll
    for (int mt = 0; mt < 4; mt++)
#pragma unroll
        for (int nt = 0; nt < WNT; nt++)
#pragma unroll
            for (int j = 0; j < 4; j++) acc[mt][nt][j] = 0.f;

    auto load_stage = [&](int kc, int buf) {
#pragma unroll
        for (int i = 0; i < 4; i++) {                 // A: 16KB
            int c = tid + i * 256;
            int t = c >> 5, o = (c & 31) * 16;
            int pl = t >> 4, kt = (t >> 3) & 1, mt = t & 7;
            const uint32_t* src = (pl ? Al : Ah) +
                ((blockIdx.x * 8 + mt) * 8 + kc * 2 + kt) * 128;
            cp16(sb + buf * STAGE + t * 512 + o, (const char*)src + o);
        }
#pragma unroll
        for (int i = 0; i < NT / 4; i++) {            // B: NT KB
            int c = tid + i * 256;
            int t = c >> 4, o = (c & 15) * 16;
            int pl = t / (2 * NT);
            int kt = (t / NT) & 1;
            int nt = t % NT;
            const uint32_t* src = (pl ? Bl : Bh) + ((kc * 2 + kt) * NT + nt) * 64;
            cp16(sb + buf * STAGE + 16384 + t * 256 + o, (const char*)src + o);
        }
        asm volatile("cp.async.commit_group;" ::: "memory");
    };

    auto compute = [&](int buf) {
#pragma unroll
        for (int kt = 0; kt < 2; kt++) {
            uint32_t a[2][4][4];
#pragma unroll
            for (int pl = 0; pl < 2; pl++)
#pragma unroll
                for (int mt = 0; mt < 4; mt++) {
                    uint32_t ad = sb + buf * STAGE +
                        (((pl * 2 + kt) * 8) + (wm * 4 + mt)) * 512 + lane * 16;
                    asm volatile("ld.shared.v4.b32 {%0,%1,%2,%3},[%4];"
                        : "=r"(a[pl][mt][0]), "=r"(a[pl][mt][1]),
                          "=r"(a[pl][mt][2]), "=r"(a[pl][mt][3]) : "r"(ad));
                }
            uint32_t b[2][WNT][2];
#pragma unroll
            for (int pl = 0; pl < 2; pl++)
#pragma unroll
                for (int nt = 0; nt < WNT; nt++) {
                    uint32_t ad = sb + buf * STAGE + 16384 +
                        ((pl * 2 + kt) * NT + wn * WNT + nt) * 256 + lane * 8;
                    asm volatile("ld.shared.v2.b32 {%0,%1},[%2];"
                        : "=r"(b[pl][nt][0]), "=r"(b[pl][nt][1]) : "r"(ad));
                }
#pragma unroll
            for (int mt = 0; mt < 4; mt++)
#pragma unroll
                for (int nt = 0; nt < WNT; nt++) {
                    MMA_BF16(acc[mt][nt], a[0][mt], b[0][nt]);  // hi*hi
                    MMA_BF16(acc[mt][nt], a[0][mt], b[1][nt]);  // hi*lo
                    MMA_BF16(acc[mt][nt], a[1][mt], b[0][nt]);  // lo*hi
                }
        }
    };

    load_stage(0, 0);
    for (int kc = 0; kc < 4; kc++) {
        if (kc < 3) {
            load_stage(kc + 1, (kc + 1) & 1);
            asm volatile("cp.async.wait_group 1;" ::: "memory");
        } else {
            asm volatile("cp.async.wait_group 0;" ::: "memory");
        }
        __syncthreads();
        compute(kc & 1);
        __syncthreads();
    }

    int gid = lane >> 2, tig = lane & 3;
#pragma unroll
    for (int mt = 0; mt < 4; mt++) {
        int row = bRow + wm * 64 + mt * 16 + gid;
#pragma unroll
        for (int nt = 0; nt < WNT; nt++) {
            int col = wn * (8 * WNT) + nt * 8 + tig * 2;
            if (row < M)
                *reinterpret_cast<float2*>(&C[row * BN + col]) =
                    make_float2(acc[mt][nt][0], acc[mt][nt][1]);
            if (row + 8 < M)
                *reinterpret_cast<float2*>(&C[(row + 8) * BN + col]) =
                    make_float2(acc[mt][nt][2], acc[mt][nt][3]);
        }
    }
}

// ---------------- aggregation: h = mean_agg(y) + bl + z, 128-ch --------------
__global__ void agg128_kernel(const float* __restrict__ y, const float* __restrict__ z,
                              const float* __restrict__ bl,
                              const int* __restrict__ ptr, const int* __restrict__ csrsrc,
                              float* __restrict__ out_relu,
                              float* __restrict__ out_pre) {
    int warpsPerBlock = blockDim.x >> 5;
    int node = blockIdx.x * warpsPerBlock + (threadIdx.x >> 5);
    if (node >= N_NODES) return;
    int lane = threadIdx.x & 31;

    int lo = ptr[node], hi = ptr[node + 1];
    float4 acc = make_float4(0.f, 0.f, 0.f, 0.f);
#pragma unroll 4
    for (int e = lo; e < hi; e++) {
        int s = csrsrc[e];
        float4 v = *reinterpret_cast<const float4*>(&y[s * 128 + lane * 4]);
        acc.x += v.x; acc.y += v.y; acc.z += v.z; acc.w += v.w;
    }
    float inv = 1.f / (float)max(hi - lo, 1);
    float4 b = *reinterpret_cast<const float4*>(&bl[lane * 4]);
    float4 zi = *reinterpret_cast<const float4*>(&z[node * 128 + lane * 4]);
    float4 h;
    h.x = acc.x * inv + b.x + zi.x;
    h.y = acc.y * inv + b.y + zi.y;
    h.z = acc.z * inv + b.z + zi.z;
    h.w = acc.w * inv + b.w + zi.w;
    if (out_pre) *reinterpret_cast<float4*>(&out_pre[node * 128 + lane * 4]) = h;
    float4 r = make_float4(fmaxf(h.x, 0.f), fmaxf(h.y, 0.f), fmaxf(h.z, 0.f), fmaxf(h.w, 0.f));
    *reinterpret_cast<float4*>(&out_relu[node * 128 + lane * 4]) = r;
}

// ---------------- final aggregation (64-ch) + log_softmax --------------------
__global__ void agg64_lsm_kernel(const float* __restrict__ y, const float* __restrict__ z,
                                 const float* __restrict__ bl,
                                 const int* __restrict__ ptr, const int* __restrict__ csrsrc,
                                 float* __restrict__ out) {
    int warpsPerBlock = blockDim.x >> 5;
    int node = blockIdx.x * warpsPerBlock + (threadIdx.x >> 5);
    if (node >= N_NODES) return;
    int lane = threadIdx.x & 31;

    int lo = ptr[node], hi = ptr[node + 1];
    float2 acc = make_float2(0.f, 0.f);
#pragma unroll 4
    for (int e = lo; e < hi; e++) {
        int s = csrsrc[e];
        float2 v = *reinterpret_cast<const float2*>(&y[s * 64 + lane * 2]);
        acc.x += v.x; acc.y += v.y;
    }
    float inv = 1.f / (float)max(hi - lo, 1);
    float2 b = *reinterpret_cast<const float2*>(&bl[lane * 2]);
    float2 zi = *reinterpret_cast<const float2*>(&z[node * 64 + lane * 2]);
    float2 h;
    h.x = acc.x * inv + b.x + zi.x;
    h.y = acc.y * inv + b.y + zi.y;

    float m = fmaxf(h.x, h.y);
#pragma unroll
    for (int off = 16; off > 0; off >>= 1)
        m = fmaxf(m, __shfl_xor_sync(0xFFFFFFFFu, m, off));
    float s = expf(h.x - m) + expf(h.y - m);
#pragma unroll
    for (int off = 16; off > 0; off >>= 1)
        s += __shfl_xor_sync(0xFFFFFFFFu, s, off);
    float ls = logf(s);
    float2 r = make_float2(h.x - m - ls, h.y - m - ls);
    *reinterpret_cast<float2*>(&out[node * 64 + lane * 2]) = r;
}

// ---------------- pooling ----------------------------------------------------
__global__ void pool_kernel(const float* __restrict__ x, const int* __restrict__ gstart,
                            float* __restrict__ gout) {
    int warpsPerBlock = blockDim.x >> 5;
    int g = blockIdx.x * warpsPerBlock + (threadIdx.x >> 5);
    if (g >= N_GRAPHS) return;
    int lane = threadIdx.x & 31;
    int lo = gstart[g], hi = gstart[g + 1];
    float4 acc = make_float4(0.f, 0.f, 0.f, 0.f);
    for (int i = lo; i < hi; i++) {
        float4 v = *reinterpret_cast<const float4*>(&x[i * 128 + lane * 4]);
        acc.x += v.x; acc.y += v.y; acc.z += v.z; acc.w += v.w;
    }
    float inv = 1.f / (float)max(hi - lo, 1);
    acc.x *= inv; acc.y *= inv; acc.z *= inv; acc.w *= inv;
    *reinterpret_cast<float4*>(&gout[g * 128 + lane * 4]) = acc;
}

// ---------------- launch -----------------------------------------------------
extern "C" void kernel_launch(void* const* d_in, const int* in_sizes, int n_in,
                              void* d_out, int out_size) {
    const float* x       = (const float*)d_in[0];
    const int*   ei      = (const int*)d_in[1];
    const int*   cluster = (const int*)d_in[2];
    const float* Wl0 = (const float*)d_in[3];
    const float* bl0 = (const float*)d_in[4];
    const float* Wr0 = (const float*)d_in[5];
    const float* Wl1 = (const float*)d_in[6];
    const float* bl1 = (const float*)d_in[7];
    const float* Wr1 = (const float*)d_in[8];
    const float* Wl2 = (const float*)d_in[9];
    const float* bl2 = (const float*)d_in[10];
    const float* Wr2 = (const float*)d_in[11];

    const int* src = ei;
    const int* dst = ei + N_EDGES;

    float* out = (float*)d_out;
    float* out_lsm = out;
    float* out_pre = out + N_NODES * C_OUT;
    float* out_g   = out + N_NODES * C_OUT + N_NODES * C_HID;

    float *y, *z, *x1, *x2;
    uint32_t *ah, *al, *wh, *wl;
    int *deg, *fill, *ptr, *csrsrc, *gstart;
    cudaGetSymbolAddress((void**)&y, g_y);
    cudaGetSymbolAddress((void**)&z, g_z);
    cudaGetSymbolAddress((void**)&x1, g_x1);
    cudaGetSymbolAddress((void**)&x2, g_x2);
    cudaGetSymbolAddress((void**)&ah, g_ah);
    cudaGetSymbolAddress((void**)&al, g_al);
    cudaGetSymbolAddress((void**)&wh, g_wh);
    cudaGetSymbolAddress((void**)&wl, g_wl);
    cudaGetSymbolAddress((void**)&deg, g_deg);
    cudaGetSymbolAddress((void**)&fill, g_fill);
    cudaGetSymbolAddress((void**)&ptr, g_ptr);
    cudaGetSymbolAddress((void**)&csrsrc, g_csrsrc);
    cudaGetSymbolAddress((void**)&gstart, g_gstart);

    const int SMEM128 = 2 * (16384 + 16384);  // 65536
    const int SMEM64  = 2 * (16384 + 8192);   // 49152
    cudaFuncSetAttribute(bf16_gemm<128>, cudaFuncAttributeMaxDynamicSharedMemorySize, SMEM128);
    cudaFuncSetAttribute(bf16_gemm<64>,  cudaFuncAttributeMaxDynamicSharedMemorySize, SMEM64);

    // ---- CSR build + weight pack (edge/weight data static across layers) ----
    zero_int2<<<128, 256>>>(deg, N_NODES, fill, N_NODES);
    hist_kernel<<<592, 256>>>(dst, deg);
    scan_kernel<<<1, 1024>>>(deg, ptr);
    fill_kernel<<<592, 256>>>(src, dst, ptr, fill, csrsrc);
    gstart_kernel<<<3, 256>>>(cluster, gstart);
    pack_w6<<<dim3(16, 6), 256>>>(Wl0, Wr0, Wl1, Wr1, Wl2, Wr2, wh, wl);

    const int GEMM_GRID = 391;
    const int AGG_BLOCKS = (N_NODES + 7) / 8;
    dim3 gg(GEMM_GRID, 2);

    // ---- layer 0 ----
    pack_a<<<MT_PAD, 256>>>(x, ah, al, N_NODES);
    bf16_gemm<128><<<gg, 256, SMEM128>>>(ah, al,
        wh + 0 * 8192, wl + 0 * 8192, wh + 1 * 8192, wl + 1 * 8192, y, z, N_NODES);
    agg128_kernel<<<AGG_BLOCKS, 256>>>(y, z, bl0, ptr, csrsrc, x1, nullptr);

    // ---- layer 1 ----
    pack_a<<<MT_PAD, 256>>>(x1, ah, al, N_NODES);
    bf16_gemm<128><<<gg, 256, SMEM128>>>(ah, al,
        wh + 2 * 8192, wl + 2 * 8192, wh + 3 * 8192, wl + 3 * 8192, y, z, N_NODES);
    agg128_kernel<<<AGG_BLOCKS, 256>>>(y, z, bl1, ptr, csrsrc, x2, out_pre);

    // ---- pooling ----
    pool_kernel<<<(N_GRAPHS + 7) / 8, 256>>>(x2, gstart, out_g);

    // ---- layer 2 + log_softmax ----
    pack_a<<<MT_PAD, 256>>>(x2, ah, al, N_NODES);
    bf16_gemm<64><<<gg, 256, SMEM64>>>(ah, al,
        wh + 4 * 8192, wl + 4 * 8192, wh + 5 * 8192, wl + 5 * 8192, y, z, N_NODES);
    agg64_lsm_kernel<<<AGG_BLOCKS, 256>>>(y, z, bl2, ptr, csrsrc, out_lsm);
}

// round 5
// speedup vs baseline: 1.6622x; 1.0229x over previous
#include <cuda_runtime.h>
#include <cuda_bf16.h>
#include <math.h>
#include <stdint.h>

#define N_NODES 50000
#define N_EDGES 600000
#define C_HID 128
#define C_OUT 64
#define N_GRAPHS 512
#define MT_PAD 3128   // 391*8 m-tiles of 16 rows (>= ceil(50000/16)=3125)

// ---------------- scratch (__device__ globals) -------------------------------
__device__ float    g_y[N_NODES * C_HID];
__device__ float    g_z[N_NODES * C_HID];
__device__ float    g_x2[N_NODES * C_HID];
__device__ uint32_t g_ah[MT_PAD * 8 * 128];   // A hi, fragment-packed bf16x2
__device__ uint32_t g_al[MT_PAD * 8 * 128];   // A lo
__device__ uint32_t g_wh[6 * 8192];           // 6 weights hi, fragment-packed
__device__ uint32_t g_wl[6 * 8192];           // 6 weights lo
__device__ int      g_deg[N_NODES];
__device__ int      g_fill[N_NODES];
__device__ int      g_ptr[N_NODES + 1];
__device__ int      g_csrsrc[N_EDGES];
__device__ int      g_gstart[N_GRAPHS + 1];

// ---------------- CSR / misc helpers -----------------------------------------
__global__ void zero_int2(int* a, int na, int* b, int nb) {
    int i = blockIdx.x * blockDim.x + threadIdx.x;
    int stride = gridDim.x * blockDim.x;
    for (int k = i; k < na; k += stride) a[k] = 0;
    for (int k = i; k < nb; k += stride) b[k] = 0;
}

// histogram over dst (int4 loads) + gstart binary search fused in
__global__ void hist_gstart_kernel(const int4* __restrict__ dst4, int* __restrict__ deg,
                                   const int* __restrict__ cluster, int* __restrict__ gstart) {
    int i = blockIdx.x * blockDim.x + threadIdx.x;
    int stride = gridDim.x * blockDim.x;
    for (int e = i; e < N_EDGES / 4; e += stride) {
        int4 d = dst4[e];
        atomicAdd(&deg[d.x], 1);
        atomicAdd(&deg[d.y], 1);
        atomicAdd(&deg[d.z], 1);
        atomicAdd(&deg[d.w], 1);
    }
    if (i <= N_GRAPHS) {
        if (i == N_GRAPHS) gstart[i] = N_NODES;
        else {
            int lo = 0, hi = N_NODES;
            while (lo < hi) {
                int mid = (lo + hi) >> 1;
                if (cluster[mid] < i) lo = mid + 1; else hi = mid;
            }
            gstart[i] = lo;
        }
    }
}

__global__ void scan_kernel(const int* __restrict__ deg, int* __restrict__ ptr) {
    __shared__ int sums[1024];
    const int CHUNK = 49;
    int t = threadIdx.x;
    int base = t * CHUNK;
    int s = 0;
    for (int j = 0; j < CHUNK; j++) {
        int i = base + j;
        if (i < N_NODES) s += deg[i];
    }
    sums[t] = s;
    __syncthreads();
    for (int off = 1; off < 1024; off <<= 1) {
        int v = (t >= off) ? sums[t - off] : 0;
        __syncthreads();
        sums[t] += v;
        __syncthreads();
    }
    int run = (t == 0) ? 0 : sums[t - 1];
    for (int j = 0; j < CHUNK; j++) {
        int i = base + j;
        if (i < N_NODES) { ptr[i] = run; run += deg[i]; }
    }
    if (t == 0) ptr[N_NODES] = N_EDGES;
}

__global__ void fill_kernel(const int4* __restrict__ src4, const int4* __restrict__ dst4,
                            const int* __restrict__ ptr, int* __restrict__ fill,
                            int* __restrict__ csrsrc) {
    int i = blockIdx.x * blockDim.x + threadIdx.x;
    int stride = gridDim.x * blockDim.x;
    for (int e = i; e < N_EDGES / 4; e += stride) {
        int4 s = src4[e];
        int4 d = dst4[e];
        csrsrc[ptr[d.x] + atomicAdd(&fill[d.x], 1)] = s.x;
        csrsrc[ptr[d.y] + atomicAdd(&fill[d.y], 1)] = s.y;
        csrsrc[ptr[d.z] + atomicAdd(&fill[d.z], 1)] = s.z;
        csrsrc[ptr[d.w] + atomicAdd(&fill[d.w], 1)] = s.w;
    }
}

// ---------------- bf16 split/pack helpers ------------------------------------
__device__ __forceinline__ uint32_t pack_split(float x, float y, uint32_t& lo) {
    __nv_bfloat16 hx = __float2bfloat16(x);
    __nv_bfloat16 hy = __float2bfloat16(y);
    float rx = x - __bfloat162float(hx);
    float ry = y - __bfloat162float(hy);
    __nv_bfloat16 lx = __float2bfloat16(rx);
    __nv_bfloat16 ly = __float2bfloat16(ry);
    uint16_t bhx = *reinterpret_cast<uint16_t*>(&hx);
    uint16_t bhy = *reinterpret_cast<uint16_t*>(&hy);
    uint16_t blx = *reinterpret_cast<uint16_t*>(&lx);
    uint16_t bly = *reinterpret_cast<uint16_t*>(&ly);
    lo = ((uint32_t)bly << 16) | blx;
    return ((uint32_t)bhy << 16) | bhx;
}

// ---- pack A [M,128] f32 -> fragment-packed hi/lo bf16x2 tiles (layer0 only) --
__global__ void pack_a(const float* __restrict__ A, uint32_t* __restrict__ Ah,
                       uint32_t* __restrict__ Al, int M) {
    int tile = blockIdx.x * 8 + (threadIdx.x >> 5);
    if (tile >= MT_PAD * 8) return;
    int mt = tile >> 3, kt = tile & 7;
    int lane = threadIdx.x & 31, gid = lane >> 2, tig = lane & 3;
    uint32_t h[4], l[4];
#pragma unroll
    for (int r = 0; r < 4; r++) {
        int row = mt * 16 + gid + (r & 1) * 8;
        int col = kt * 16 + tig * 2 + (r >> 1) * 8;
        float2 v = make_float2(0.f, 0.f);
        if (row < M) v = *reinterpret_cast<const float2*>(&A[row * 128 + col]);
        h[r] = pack_split(v.x, v.y, l[r]);
    }
    *reinterpret_cast<uint4*>(&Ah[(tile * 32 + lane) * 4]) = make_uint4(h[0], h[1], h[2], h[3]);
    *reinterpret_cast<uint4*>(&Al[(tile * 32 + lane) * 4]) = make_uint4(l[0], l[1], l[2], l[3]);
}

// ---- pack 6 weight matrices -> fragment-packed hi/lo (B layout, col-major) --
__global__ void pack_w6(const float* W0, const float* W1, const float* W2,
                        const float* W3, const float* W4, const float* W5,
                        uint32_t* __restrict__ Wh, uint32_t* __restrict__ Wl) {
    int mat = blockIdx.y;
    const float* W;
    int BN;
    switch (mat) {
        case 0: W = W0; BN = 128; break;
        case 1: W = W1; BN = 128; break;
        case 2: W = W2; BN = 128; break;
        case 3: W = W3; BN = 128; break;
        case 4: W = W4; BN = 64; break;
        default: W = W5; BN = 64; break;
    }
    int NT = BN / 8;
    int tile = blockIdx.x * 8 + (threadIdx.x >> 5);
    if (tile >= 8 * NT) return;
    int kt = tile / NT, nt = tile % NT;
    int lane = threadIdx.x & 31, gid = lane >> 2, tig = lane & 3;
    int col = nt * 8 + gid;
    uint32_t h[2], l[2];
#pragma unroll
    for (int r = 0; r < 2; r++) {
        int k = kt * 16 + tig * 2 + r * 8;
        float v0 = W[k * BN + col];
        float v1 = W[(k + 1) * BN + col];
        h[r] = pack_split(v0, v1, l[r]);
    }
    *reinterpret_cast<uint2*>(&Wh[mat * 8192 + (tile * 32 + lane) * 2]) = make_uint2(h[0], h[1]);
    *reinterpret_cast<uint2*>(&Wl[mat * 8192 + (tile * 32 + lane) * 2]) = make_uint2(l[0], l[1]);
}

// ---------------- bf16 split GEMM --------------------------------------------
__device__ __forceinline__ uint32_t smem_u32(const void* p) {
    uint32_t a;
    asm("{ .reg .u64 t; cvta.to.shared.u64 t, %1; cvt.u32.u64 %0, t; }" : "=r"(a) : "l"(p));
    return a;
}

__device__ __forceinline__ void cp16(uint32_t dst, const void* src) {
    asm volatile("cp.async.cg.shared.global [%0], [%1], 16;" :: "r"(dst), "l"(src) : "memory");
}

#define MMA_BF16(c, a, b)                                                         \
    asm volatile(                                                                 \
        "mma.sync.aligned.m16n8k16.row.col.f32.bf16.bf16.f32 "                    \
        "{%0,%1,%2,%3},{%4,%5,%6,%7},{%8,%9},{%0,%1,%2,%3};"                      \
        : "+f"(c[0]), "+f"(c[1]), "+f"(c[2]), "+f"(c[3])                          \
        : "r"(a[0]), "r"(a[1]), "r"(a[2]), "r"(a[3]), "r"(b[0]), "r"(b[1]))

template <int BN>
__global__ __launch_bounds__(256, 2) void bf16_gemm(
    const uint32_t* __restrict__ Ah, const uint32_t* __restrict__ Al,
    const uint32_t* __restrict__ Bh0, const uint32_t* __restrict__ Bl0,
    const uint32_t* __restrict__ Bh1, const uint32_t* __restrict__ Bl1,
    float* __restrict__ C0, float* __restrict__ C1, int M) {
    constexpr int NT = BN / 8;
    constexpr int WNT = NT / 4;
    constexpr int STAGE = 16384 + NT * 1024;
    extern __shared__ char smem[];

    const uint32_t* Bh = blockIdx.y ? Bh1 : Bh0;
    const uint32_t* Bl = blockIdx.y ? Bl1 : Bl0;
    float* C = blockIdx.y ? C1 : C0;

    uint32_t sb = smem_u32(smem);
    int tid = threadIdx.x, lane = tid & 31, warp = tid >> 5;
    int wm = warp & 1, wn = warp >> 1;
    int bRow = blockIdx.x * 128;

    float acc[4][WNT][4];
#pragma unroll
    for (int mt = 0; mt < 4; mt++)
#pragma unroll
        for (int nt = 0; nt < WNT; nt++)
#pragma unroll
            for (int j = 0; j < 4; j++) acc[mt][nt][j] = 0.f;

    auto load_stage = [&](int kc, int buf) {
#pragma unroll
        for (int i = 0; i < 4; i++) {                 // A: 16KB
            int c = tid + i * 256;
            int t = c >> 5, o = (c & 31) * 16;
            int pl = t >> 4, kt = (t >> 3) & 1, mt = t & 7;
            const uint32_t* src = (pl ? Al : Ah) +
                ((blockIdx.x * 8 + mt) * 8 + kc * 2 + kt) * 128;
            cp16(sb + buf * STAGE + t * 512 + o, (const char*)src + o);
        }
#pragma unroll
        for (int i = 0; i < NT / 4; i++) {            // B: NT KB
            int c = tid + i * 256;
            int t = c >> 4, o = (c & 15) * 16;
            int pl = t / (2 * NT);
            int kt = (t / NT) & 1;
            int nt = t % NT;
            const uint32_t* src = (pl ? Bl : Bh) + ((kc * 2 + kt) * NT + nt) * 64;
            cp16(sb + buf * STAGE + 16384 + t * 256 + o, (const char*)src + o);
        }
        asm volatile("cp.async.commit_group;" ::: "memory");
    };

    auto compute = [&](int buf) {
#pragma unroll
        for (int kt = 0; kt < 2; kt++) {
            uint32_t a[2][4][4];
#pragma unroll
            for (int pl = 0; pl < 2; pl++)
#pragma unroll
                for (int mt = 0; mt < 4; mt++) {
                    uint32_t ad = sb + buf * STAGE +
                        (((pl * 2 + kt) * 8) + (wm * 4 + mt)) * 512 + lane * 16;
                    asm volatile("ld.shared.v4.b32 {%0,%1,%2,%3},[%4];"
                        : "=r"(a[pl][mt][0]), "=r"(a[pl][mt][1]),
                          "=r"(a[pl][mt][2]), "=r"(a[pl][mt][3]) : "r"(ad));
                }
            uint32_t b[2][WNT][2];
#pragma unroll
            for (int pl = 0; pl < 2; pl++)
#pragma unroll
                for (int nt = 0; nt < WNT; nt++) {
                    uint32_t ad = sb + buf * STAGE + 16384 +
                        ((pl * 2 + kt) * NT + wn * WNT + nt) * 256 + lane * 8;
                    asm volatile("ld.shared.v2.b32 {%0,%1},[%2];"
                        : "=r"(b[pl][nt][0]), "=r"(b[pl][nt][1]) : "r"(ad));
                }
#pragma unroll
            for (int mt = 0; mt < 4; mt++)
#pragma unroll
                for (int nt = 0; nt < WNT; nt++) {
                    MMA_BF16(acc[mt][nt], a[0][mt], b[0][nt]);  // hi*hi
                    MMA_BF16(acc[mt][nt], a[0][mt], b[1][nt]);  // hi*lo
                    MMA_BF16(acc[mt][nt], a[1][mt], b[0][nt]);  // lo*hi
                }
        }
    };

    load_stage(0, 0);
    for (int kc = 0; kc < 4; kc++) {
        if (kc < 3) {
            load_stage(kc + 1, (kc + 1) & 1);
            asm volatile("cp.async.wait_group 1;" ::: "memory");
        } else {
            asm volatile("cp.async.wait_group 0;" ::: "memory");
        }
        __syncthreads();
        compute(kc & 1);
        __syncthreads();
    }

    int gid = lane >> 2, tig = lane & 3;
#pragma unroll
    for (int mt = 0; mt < 4; mt++) {
        int row = bRow + wm * 64 + mt * 16 + gid;
#pragma unroll
        for (int nt = 0; nt < WNT; nt++) {
            int col = wn * (8 * WNT) + nt * 8 + tig * 2;
            if (row < M)
                *reinterpret_cast<float2*>(&C[row * BN + col]) =
                    make_float2(acc[mt][nt][0], acc[mt][nt][1]);
            if (row + 8 < M)
                *reinterpret_cast<float2*>(&C[(row + 8) * BN + col]) =
                    make_float2(acc[mt][nt][2], acc[mt][nt][3]);
        }
    }
}

// ------- aggregation + fused fragment-packing of relu output -----------------
// h = mean_agg(y) + bl + z ; pack relu(h) directly as next layer's A operand.
__global__ void agg128_pack_kernel(const float* __restrict__ y, const float* __restrict__ z,
                                   const float* __restrict__ bl,
                                   const int* __restrict__ ptr, const int* __restrict__ csrsrc,
                                   uint32_t* __restrict__ Ah, uint32_t* __restrict__ Al,
                                   float* __restrict__ out_pre,   // optional (layer1 "out")
                                   float* __restrict__ out_f32) { // optional (x2 for pooling)
    int warpsPerBlock = blockDim.x >> 5;
    int node = blockIdx.x * warpsPerBlock + (threadIdx.x >> 5);
    if (node >= N_NODES) return;
    int lane = threadIdx.x & 31;

    int lo = ptr[node], hi = ptr[node + 1];
    float4 acc = make_float4(0.f, 0.f, 0.f, 0.f);
#pragma unroll 4
    for (int e = lo; e < hi; e++) {
        int s = csrsrc[e];
        float4 v = *reinterpret_cast<const float4*>(&y[s * 128 + lane * 4]);
        acc.x += v.x; acc.y += v.y; acc.z += v.z; acc.w += v.w;
    }
    float inv = 1.f / (float)max(hi - lo, 1);
    float4 b = *reinterpret_cast<const float4*>(&bl[lane * 4]);
    float4 zi = *reinterpret_cast<const float4*>(&z[node * 128 + lane * 4]);
    float4 h;
    h.x = acc.x * inv + b.x + zi.x;
    h.y = acc.y * inv + b.y + zi.y;
    h.z = acc.z * inv + b.z + zi.z;
    h.w = acc.w * inv + b.w + zi.w;
    if (out_pre) *reinterpret_cast<float4*>(&out_pre[node * 128 + lane * 4]) = h;
    float4 r = make_float4(fmaxf(h.x, 0.f), fmaxf(h.y, 0.f), fmaxf(h.z, 0.f), fmaxf(h.w, 0.f));
    if (out_f32) *reinterpret_cast<float4*>(&out_f32[node * 128 + lane * 4]) = r;

    // fragment-packed store: row = node, cols = lane*4 .. lane*4+3
    int mt = node >> 4, gid = node & 7, rowhalf = (node >> 3) & 1;
    int kt = lane >> 2;
    float v01[2] = {r.x, r.z};
    float v11[2] = {r.y, r.w};
#pragma unroll
    for (int p = 0; p < 2; p++) {
        int c = lane * 4 + 2 * p;
        int ct = c & 15;
        int tig = (ct & 7) >> 1;
        int colhalf = ct >> 3;
        int reg = rowhalf + 2 * colhalf;
        int idx = ((mt * 8 + kt) * 32 + gid * 4 + tig) * 4 + reg;
        uint32_t lo32;
        uint32_t hi32 = pack_split(v01[p], v11[p], lo32);
        Ah[idx] = hi32;
        Al[idx] = lo32;
    }
}

// ---------------- final aggregation (64-ch) + log_softmax --------------------
__global__ void agg64_lsm_kernel(const float* __restrict__ y, const float* __restrict__ z,
                                 const float* __restrict__ bl,
                                 const int* __restrict__ ptr, const int* __restrict__ csrsrc,
                                 float* __restrict__ out) {
    int warpsPerBlock = blockDim.x >> 5;
    int node = blockIdx.x * warpsPerBlock + (threadIdx.x >> 5);
    if (node >= N_NODES) return;
    int lane = threadIdx.x & 31;

    int lo = ptr[node], hi = ptr[node + 1];
    float2 acc = make_float2(0.f, 0.f);
#pragma unroll 4
    for (int e = lo; e < hi; e++) {
        int s = csrsrc[e];
        float2 v = *reinterpret_cast<const float2*>(&y[s * 64 + lane * 2]);
        acc.x += v.x; acc.y += v.y;
    }
    float inv = 1.f / (float)max(hi - lo, 1);
    float2 b = *reinterpret_cast<const float2*>(&bl[lane * 2]);
    float2 zi = *reinterpret_cast<const float2*>(&z[node * 64 + lane * 2]);
    float2 h;
    h.x = acc.x * inv + b.x + zi.x;
    h.y = acc.y * inv + b.y + zi.y;

    float m = fmaxf(h.x, h.y);
#pragma unroll
    for (int off = 16; off > 0; off >>= 1)
        m = fmaxf(m, __shfl_xor_sync(0xFFFFFFFFu, m, off));
    float s = expf(h.x - m) + expf(h.y - m);
#pragma unroll
    for (int off = 16; off > 0; off >>= 1)
        s += __shfl_xor_sync(0xFFFFFFFFu, s, off);
    float ls = logf(s);
    float2 r = make_float2(h.x - m - ls, h.y - m - ls);
    *reinterpret_cast<float2*>(&out[node * 64 + lane * 2]) = r;
}

// ---------------- pooling ----------------------------------------------------
__global__ void pool_kernel(const float* __restrict__ x, const int* __restrict__ gstart,
                            float* __restrict__ gout) {
    int warpsPerBlock = blockDim.x >> 5;
    int g = blockIdx.x * warpsPerBlock + (threadIdx.x >> 5);
    if (g >= N_GRAPHS) return;
    int lane = threadIdx.x & 31;
    int lo = gstart[g], hi = gstart[g + 1];
    float4 acc = make_float4(0.f, 0.f, 0.f, 0.f);
    for (int i = lo; i < hi; i++) {
        float4 v = *reinterpret_cast<const float4*>(&x[i * 128 + lane * 4]);
        acc.x += v.x; acc.y += v.y; acc.z += v.z; acc.w += v.w;
    }
    float inv = 1.f / (float)max(hi - lo, 1);
    acc.x *= inv; acc.y *= inv; acc.z *= inv; acc.w *= inv;
    *reinterpret_cast<float4*>(&gout[g * 128 + lane * 4]) = acc;
}

// ---------------- launch -----------------------------------------------------
extern "C" void kernel_launch(void* const* d_in, const int* in_sizes, int n_in,
                              void* d_out, int out_size) {
    const float* x       = (const float*)d_in[0];
    const int*   ei      = (const int*)d_in[1];
    const int*   cluster = (const int*)d_in[2];
    const float* Wl0 = (const float*)d_in[3];
    const float* bl0 = (const float*)d_in[4];
    const float* Wr0 = (const float*)d_in[5];
    const float* Wl1 = (const float*)d_in[6];
    const float* bl1 = (const float*)d_in[7];
    const float* Wr1 = (const float*)d_in[8];
    const float* Wl2 = (const float*)d_in[9];
    const float* bl2 = (const float*)d_in[10];
    const float* Wr2 = (const float*)d_in[11];

    const int* src = ei;
    const int* dst = ei + N_EDGES;

    float* out = (float*)d_out;
    float* out_lsm = out;
    float* out_pre = out + N_NODES * C_OUT;
    float* out_g   = out + N_NODES * C_OUT + N_NODES * C_HID;

    float *y, *z, *x2;
    uint32_t *ah, *al, *wh, *wl;
    int *deg, *fill, *ptr, *csrsrc, *gstart;
    cudaGetSymbolAddress((void**)&y, g_y);
    cudaGetSymbolAddress((void**)&z, g_z);
    cudaGetSymbolAddress((void**)&x2, g_x2);
    cudaGetSymbolAddress((void**)&ah, g_ah);
    cudaGetSymbolAddress((void**)&al, g_al);
    cudaGetSymbolAddress((void**)&wh, g_wh);
    cudaGetSymbolAddress((void**)&wl, g_wl);
    cudaGetSymbolAddress((void**)&deg, g_deg);
    cudaGetSymbolAddress((void**)&fill, g_fill);
    cudaGetSymbolAddress((void**)&ptr, g_ptr);
    cudaGetSymbolAddress((void**)&csrsrc, g_csrsrc);
    cudaGetSymbolAddress((void**)&gstart, g_gstart);

    const int SMEM128 = 2 * (16384 + 16384);  // 65536
    const int SMEM64  = 2 * (16384 + 8192);   // 49152
    cudaFuncSetAttribute(bf16_gemm<128>, cudaFuncAttributeMaxDynamicSharedMemorySize, SMEM128);
    cudaFuncSetAttribute(bf16_gemm<64>,  cudaFuncAttributeMaxDynamicSharedMemorySize, SMEM64);

    // ---- CSR build + packing of static data ----
    zero_int2<<<128, 256>>>(deg, N_NODES, fill, N_NODES);
    hist_gstart_kernel<<<296, 256>>>((const int4*)dst, deg, cluster, gstart);
    scan_kernel<<<1, 1024>>>(deg, ptr);
    fill_kernel<<<296, 256>>>((const int4*)src, (const int4*)dst, ptr, fill, csrsrc);
    pack_w6<<<dim3(16, 6), 256>>>(Wl0, Wr0, Wl1, Wr1, Wl2, Wr2, wh, wl);
    pack_a<<<MT_PAD, 256>>>(x, ah, al, N_NODES);

    const int GEMM_GRID = 391;
    const int AGG_BLOCKS = (N_NODES + 7) / 8;
    dim3 gg(GEMM_GRID, 2);

    // ---- layer 0 (relu output lives only in packed form) ----
    bf16_gemm<128><<<gg, 256, SMEM128>>>(ah, al,
        wh + 0 * 8192, wl + 0 * 8192, wh + 1 * 8192, wl + 1 * 8192, y, z, N_NODES);
    agg128_pack_kernel<<<AGG_BLOCKS, 256>>>(y, z, bl0, ptr, csrsrc, ah, al,
                                            nullptr, nullptr);

    // ---- layer 1 (pre-relu "out" + f32 x2 for pooling + packed A) ----
    bf16_gemm<128><<<gg, 256, SMEM128>>>(ah, al,
        wh + 2 * 8192, wl + 2 * 8192, wh + 3 * 8192, wl + 3 * 8192, y, z, N_NODES);
    agg128_pack_kernel<<<AGG_BLOCKS, 256>>>(y, z, bl1, ptr, csrsrc, ah, al,
                                            out_pre, x2);

    // ---- pooling ----
    pool_kernel<<<(N_GRAPHS + 7) / 8, 256>>>(x2, gstart, out_g);

    // ---- layer 2 + log_softmax ----
    bf16_gemm<64><<<gg, 256, SMEM64>>>(ah, al,
        wh + 4 * 8192, wl + 4 * 8192, wh + 5 * 8192, wl + 5 * 8192, y, z, N_NODES);
    agg64_lsm_kernel<<<AGG_BLOCKS, 256>>>(y, z, bl2, ptr, csrsrc, out_lsm);
}

// round 6
// speedup vs baseline: 1.6632x; 1.0006x over previous
#include <cuda_runtime.h>
#include <cuda_bf16.h>
#include <math.h>
#include <stdint.h>

#define N_NODES 50000
#define N_EDGES 600000
#define C_HID 128
#define C_OUT 64
#define N_GRAPHS 512
#define MT_PAD 3128   // 391*8 m-tiles of 16 rows (>= ceil(50000/16)=3125)

// ---------------- scratch (__device__ globals) -------------------------------
__device__ float    g_y[N_NODES * C_HID];
__device__ float    g_z[N_NODES * C_HID];
__device__ float    g_x2[N_NODES * C_HID];
__device__ uint32_t g_ah[MT_PAD * 8 * 128];   // A hi, fragment-packed bf16x2
__device__ uint32_t g_al[MT_PAD * 8 * 128];   // A lo
__device__ uint32_t g_wh[5 * 8192];           // weights hi (mat4 = [Wl2|Wr2] fused)
__device__ uint32_t g_wl[5 * 8192];           // weights lo
__device__ int      g_deg[N_NODES];
__device__ int      g_fill[N_NODES];
__device__ int      g_ptr[N_NODES + 1];
__device__ int      g_csrsrc[N_EDGES];
__device__ int      g_gstart[N_GRAPHS + 1];

// ---------------- CSR helpers -------------------------------------------------
// 1 edge per thread histogram + gstart binary search fused in
__global__ void hist_gstart_kernel(const int* __restrict__ dst, int* __restrict__ deg,
                                   const int* __restrict__ cluster, int* __restrict__ gstart) {
    int i = blockIdx.x * blockDim.x + threadIdx.x;
    if (i < N_EDGES) atomicAdd(&deg[dst[i]], 1);
    if (i <= N_GRAPHS) {
        if (i == N_GRAPHS) gstart[i] = N_NODES;
        else {
            int lo = 0, hi = N_NODES;
            while (lo < hi) {
                int mid = (lo + hi) >> 1;
                if (cluster[mid] < i) lo = mid + 1; else hi = mid;
            }
            gstart[i] = lo;
        }
    }
}

__global__ void scan_kernel(const int* __restrict__ deg, int* __restrict__ ptr) {
    __shared__ int sums[1024];
    const int CHUNK = 49;
    int t = threadIdx.x;
    int base = t * CHUNK;
    int s = 0;
    for (int j = 0; j < CHUNK; j++) {
        int i = base + j;
        if (i < N_NODES) s += deg[i];
    }
    sums[t] = s;
    __syncthreads();
    for (int off = 1; off < 1024; off <<= 1) {
        int v = (t >= off) ? sums[t - off] : 0;
        __syncthreads();
        sums[t] += v;
        __syncthreads();
    }
    int run = (t == 0) ? 0 : sums[t - 1];
    for (int j = 0; j < CHUNK; j++) {
        int i = base + j;
        if (i < N_NODES) { ptr[i] = run; run += deg[i]; }
    }
    if (t == 0) ptr[N_NODES] = N_EDGES;
}

__global__ void fill_kernel(const int* __restrict__ src, const int* __restrict__ dst,
                            const int* __restrict__ ptr, int* __restrict__ fill,
                            int* __restrict__ csrsrc) {
    int i = blockIdx.x * blockDim.x + threadIdx.x;
    if (i >= N_EDGES) return;
    int d = dst[i];
    int pos = ptr[d] + atomicAdd(&fill[d], 1);
    csrsrc[pos] = src[i];
}

// ---------------- bf16 split/pack helpers ------------------------------------
__device__ __forceinline__ uint32_t pack_split(float x, float y, uint32_t& lo) {
    __nv_bfloat16 hx = __float2bfloat16(x);
    __nv_bfloat16 hy = __float2bfloat16(y);
    float rx = x - __bfloat162float(hx);
    float ry = y - __bfloat162float(hy);
    __nv_bfloat16 lx = __float2bfloat16(rx);
    __nv_bfloat16 ly = __float2bfloat16(ry);
    uint16_t bhx = *reinterpret_cast<uint16_t*>(&hx);
    uint16_t bhy = *reinterpret_cast<uint16_t*>(&hy);
    uint16_t blx = *reinterpret_cast<uint16_t*>(&lx);
    uint16_t bly = *reinterpret_cast<uint16_t*>(&ly);
    lo = ((uint32_t)bly << 16) | blx;
    return ((uint32_t)bhy << 16) | bhx;
}

// ---- pack A [M,128] f32 -> fragment-packed hi/lo bf16x2 tiles (layer0 only) --
__global__ void pack_a(const float* __restrict__ A, uint32_t* __restrict__ Ah,
                       uint32_t* __restrict__ Al, int M) {
    int tile = blockIdx.x * 8 + (threadIdx.x >> 5);
    if (tile >= MT_PAD * 8) return;
    int mt = tile >> 3, kt = tile & 7;
    int lane = threadIdx.x & 31, gid = lane >> 2, tig = lane & 3;
    uint32_t h[4], l[4];
#pragma unroll
    for (int r = 0; r < 4; r++) {
        int row = mt * 16 + gid + (r & 1) * 8;
        int col = kt * 16 + tig * 2 + (r >> 1) * 8;
        float2 v = make_float2(0.f, 0.f);
        if (row < M) v = *reinterpret_cast<const float2*>(&A[row * 128 + col]);
        h[r] = pack_split(v.x, v.y, l[r]);
    }
    *reinterpret_cast<uint4*>(&Ah[(tile * 32 + lane) * 4]) = make_uint4(h[0], h[1], h[2], h[3]);
    *reinterpret_cast<uint4*>(&Al[(tile * 32 + lane) * 4]) = make_uint4(l[0], l[1], l[2], l[3]);
}

// ---- pack weights: mats 0-3 = 128-wide; mats 4,5 (64-wide) fuse into slot 4 --
__global__ void pack_w6(const float* W0, const float* W1, const float* W2,
                        const float* W3, const float* W4, const float* W5,
                        uint32_t* __restrict__ Wh, uint32_t* __restrict__ Wl) {
    int mat = blockIdx.y;
    const float* W;
    int BNs, dst_mat, nt_off;
    switch (mat) {
        case 0: W = W0; BNs = 128; dst_mat = 0; nt_off = 0; break;
        case 1: W = W1; BNs = 128; dst_mat = 1; nt_off = 0; break;
        case 2: W = W2; BNs = 128; dst_mat = 2; nt_off = 0; break;
        case 3: W = W3; BNs = 128; dst_mat = 3; nt_off = 0; break;
        case 4: W = W4; BNs = 64;  dst_mat = 4; nt_off = 0; break;
        default: W = W5; BNs = 64; dst_mat = 4; nt_off = 8; break;
    }
    int NTs = BNs / 8;
    int tile = blockIdx.x * 8 + (threadIdx.x >> 5);
    if (tile >= 8 * NTs) return;
    int kt = tile / NTs, nt = tile % NTs;
    int lane = threadIdx.x & 31, gid = lane >> 2, tig = lane & 3;
    int col = nt * 8 + gid;
    uint32_t h[2], l[2];
#pragma unroll
    for (int r = 0; r < 2; r++) {
        int k = kt * 16 + tig * 2 + r * 8;
        float v0 = W[k * BNs + col];
        float v1 = W[(k + 1) * BNs + col];
        h[r] = pack_split(v0, v1, l[r]);
    }
    int didx = dst_mat * 8192 + (kt * 16 + nt + nt_off) * 64 + lane * 2;
    *reinterpret_cast<uint2*>(&Wh[didx]) = make_uint2(h[0], h[1]);
    *reinterpret_cast<uint2*>(&Wl[didx]) = make_uint2(l[0], l[1]);
}

// ---------------- bf16 split GEMM --------------------------------------------
__device__ __forceinline__ uint32_t smem_u32(const void* p) {
    uint32_t a;
    asm("{ .reg .u64 t; cvta.to.shared.u64 t, %1; cvt.u32.u64 %0, t; }" : "=r"(a) : "l"(p));
    return a;
}

__device__ __forceinline__ void cp16(uint32_t dst, const void* src) {
    asm volatile("cp.async.cg.shared.global [%0], [%1], 16;" :: "r"(dst), "l"(src) : "memory");
}

#define MMA_BF16(c, a, b)                                                         \
    asm volatile(                                                                 \
        "mma.sync.aligned.m16n8k16.row.col.f32.bf16.bf16.f32 "                    \
        "{%0,%1,%2,%3},{%4,%5,%6,%7},{%8,%9},{%0,%1,%2,%3};"                      \
        : "+f"(c[0]), "+f"(c[1]), "+f"(c[2]), "+f"(c[3])                          \
        : "r"(a[0]), "r"(a[1]), "r"(a[2]), "r"(a[3]), "r"(b[0]), "r"(b[1]))

// C[M,128] = A[M,128] @ W[128,128]; blockIdx.y selects (W,C) pair.
__global__ __launch_bounds__(256, 2) void bf16_gemm(
    const uint32_t* __restrict__ Ah, const uint32_t* __restrict__ Al,
    const uint32_t* __restrict__ Bh0, const uint32_t* __restrict__ Bl0,
    const uint32_t* __restrict__ Bh1, const uint32_t* __restrict__ Bl1,
    float* __restrict__ C0, float* __restrict__ C1, int M) {
    constexpr int NT = 16;
    constexpr int WNT = 4;
    constexpr int STAGE = 16384 + NT * 1024;
    extern __shared__ char smem[];

    const uint32_t* Bh = blockIdx.y ? Bh1 : Bh0;
    const uint32_t* Bl = blockIdx.y ? Bl1 : Bl0;
    float* C = blockIdx.y ? C1 : C0;

    uint32_t sb = smem_u32(smem);
    int tid = threadIdx.x, lane = tid & 31, warp = tid >> 5;
    int wm = warp & 1, wn = warp >> 1;
    int bRow = blockIdx.x * 128;

    float acc[4][WNT][4];
#pragma unroll
    for (int mt = 0; mt < 4; mt++)
#pragma unroll
        for (int nt = 0; nt < WNT; nt++)
#pragma unroll
            for (int j = 0; j < 4; j++) acc[mt][nt][j] = 0.f;

    auto load_stage = [&](int kc, int buf) {
#pragma unroll
        for (int i = 0; i < 4; i++) {                 // A: 16KB
            int c = tid + i * 256;
            int t = c >> 5, o = (c & 31) * 16;
            int pl = t >> 4, kt = (t >> 3) & 1, mt = t & 7;
            const uint32_t* src = (pl ? Al : Ah) +
                ((blockIdx.x * 8 + mt) * 8 + kc * 2 + kt) * 128;
            cp16(sb + buf * STAGE + t * 512 + o, (const char*)src + o);
        }
#pragma unroll
        for (int i = 0; i < NT / 4; i++) {            // B: 16KB
            int c = tid + i * 256;
            int t = c >> 4, o = (c & 15) * 16;
            int pl = t / (2 * NT);
            int kt = (t / NT) & 1;
            int nt = t % NT;
            const uint32_t* src = (pl ? Bl : Bh) + ((kc * 2 + kt) * NT + nt) * 64;
            cp16(sb + buf * STAGE + 16384 + t * 256 + o, (const char*)src + o);
        }
        asm volatile("cp.async.commit_group;" ::: "memory");
    };

    auto compute = [&](int buf) {
#pragma unroll
        for (int kt = 0; kt < 2; kt++) {
            uint32_t a[2][4][4];
#pragma unroll
            for (int pl = 0; pl < 2; pl++)
#pragma unroll
                for (int mt = 0; mt < 4; mt++) {
                    uint32_t ad = sb + buf * STAGE +
                        (((pl * 2 + kt) * 8) + (wm * 4 + mt)) * 512 + lane * 16;
                    asm volatile("ld.shared.v4.b32 {%0,%1,%2,%3},[%4];"
                        : "=r"(a[pl][mt][0]), "=r"(a[pl][mt][1]),
                          "=r"(a[pl][mt][2]), "=r"(a[pl][mt][3]) : "r"(ad));
                }
            uint32_t b[2][WNT][2];
#pragma unroll
            for (int pl = 0; pl < 2; pl++)
#pragma unroll
                for (int nt = 0; nt < WNT; nt++) {
                    uint32_t ad = sb + buf * STAGE + 16384 +
                        ((pl * 2 + kt) * NT + wn * WNT + nt) * 256 + lane * 8;
                    asm volatile("ld.shared.v2.b32 {%0,%1},[%2];"
                        : "=r"(b[pl][nt][0]), "=r"(b[pl][nt][1]) : "r"(ad));
                }
#pragma unroll
            for (int mt = 0; mt < 4; mt++)
#pragma unroll
                for (int nt = 0; nt < WNT; nt++) {
                    MMA_BF16(acc[mt][nt], a[0][mt], b[0][nt]);  // hi*hi
                    MMA_BF16(acc[mt][nt], a[0][mt], b[1][nt]);  // hi*lo
                    MMA_BF16(acc[mt][nt], a[1][mt], b[0][nt]);  // lo*hi
                }
        }
    };

    load_stage(0, 0);
    for (int kc = 0; kc < 4; kc++) {
        if (kc < 3) {
            load_stage(kc + 1, (kc + 1) & 1);
            asm volatile("cp.async.wait_group 1;" ::: "memory");
        } else {
            asm volatile("cp.async.wait_group 0;" ::: "memory");
        }
        __syncthreads();
        compute(kc & 1);
        __syncthreads();
    }

    int gid = lane >> 2, tig = lane & 3;
#pragma unroll
    for (int mt = 0; mt < 4; mt++) {
        int row = bRow + wm * 64 + mt * 16 + gid;
#pragma unroll
        for (int nt = 0; nt < WNT; nt++) {
            int col = wn * (8 * WNT) + nt * 8 + tig * 2;
            if (row < M)
                *reinterpret_cast<float2*>(&C[row * 128 + col]) =
                    make_float2(acc[mt][nt][0], acc[mt][nt][1]);
            if (row + 8 < M)
                *reinterpret_cast<float2*>(&C[(row + 8) * 128 + col]) =
                    make_float2(acc[mt][nt][2], acc[mt][nt][3]);
        }
    }
}

// ------- aggregation + fused fragment-packing of relu output -----------------
__global__ void agg128_pack_kernel(const float* __restrict__ y, const float* __restrict__ z,
                                   const float* __restrict__ bl,
                                   const int* __restrict__ ptr, const int* __restrict__ csrsrc,
                                   uint32_t* __restrict__ Ah, uint32_t* __restrict__ Al,
                                   float* __restrict__ out_pre,
                                   float* __restrict__ out_f32) {
    int warpsPerBlock = blockDim.x >> 5;
    int node = blockIdx.x * warpsPerBlock + (threadIdx.x >> 5);
    if (node >= N_NODES) return;
    int lane = threadIdx.x & 31;

    int lo = ptr[node], hi = ptr[node + 1];
    float4 acc = make_float4(0.f, 0.f, 0.f, 0.f);
#pragma unroll 4
    for (int e = lo; e < hi; e++) {
        int s = csrsrc[e];
        float4 v = *reinterpret_cast<const float4*>(&y[s * 128 + lane * 4]);
        acc.x += v.x; acc.y += v.y; acc.z += v.z; acc.w += v.w;
    }
    float inv = 1.f / (float)max(hi - lo, 1);
    float4 b = *reinterpret_cast<const float4*>(&bl[lane * 4]);
    float4 zi = *reinterpret_cast<const float4*>(&z[node * 128 + lane * 4]);
    float4 h;
    h.x = acc.x * inv + b.x + zi.x;
    h.y = acc.y * inv + b.y + zi.y;
    h.z = acc.z * inv + b.z + zi.z;
    h.w = acc.w * inv + b.w + zi.w;
    if (out_pre) *reinterpret_cast<float4*>(&out_pre[node * 128 + lane * 4]) = h;
    float4 r = make_float4(fmaxf(h.x, 0.f), fmaxf(h.y, 0.f), fmaxf(h.z, 0.f), fmaxf(h.w, 0.f));
    if (out_f32) *reinterpret_cast<float4*>(&out_f32[node * 128 + lane * 4]) = r;

    int mt = node >> 4, gid = node & 7, rowhalf = (node >> 3) & 1;
    int kt = lane >> 2;
    float v01[2] = {r.x, r.z};
    float v11[2] = {r.y, r.w};
#pragma unroll
    for (int p = 0; p < 2; p++) {
        int c = lane * 4 + 2 * p;
        int ct = c & 15;
        int tig = (ct & 7) >> 1;
        int colhalf = ct >> 3;
        int reg = rowhalf + 2 * colhalf;
        int idx = ((mt * 8 + kt) * 32 + gid * 4 + tig) * 4 + reg;
        uint32_t lo32;
        uint32_t hi32 = pack_split(v01[p], v11[p], lo32);
        Ah[idx] = hi32;
        Al[idx] = lo32;
    }
}

// ------- final aggregation (64-ch, interleaved y|z input) + log_softmax ------
__global__ void agg64_lsm_kernel(const float* __restrict__ yz,
                                 const float* __restrict__ bl,
                                 const int* __restrict__ ptr, const int* __restrict__ csrsrc,
                                 float* __restrict__ out) {
    int warpsPerBlock = blockDim.x >> 5;
    int node = blockIdx.x * warpsPerBlock + (threadIdx.x >> 5);
    if (node >= N_NODES) return;
    int lane = threadIdx.x & 31;

    int lo = ptr[node], hi = ptr[node + 1];
    float2 acc = make_float2(0.f, 0.f);
#pragma unroll 4
    for (int e = lo; e < hi; e++) {
        int s = csrsrc[e];
        float2 v = *reinterpret_cast<const float2*>(&yz[s * 128 + lane * 2]);
        acc.x += v.x; acc.y += v.y;
    }
    float inv = 1.f / (float)max(hi - lo, 1);
    float2 b = *reinterpret_cast<const float2*>(&bl[lane * 2]);
    float2 zi = *reinterpret_cast<const float2*>(&yz[node * 128 + 64 + lane * 2]);
    float2 h;
    h.x = acc.x * inv + b.x + zi.x;
    h.y = acc.y * inv + b.y + zi.y;

    float m = fmaxf(h.x, h.y);
#pragma unroll
    for (int off = 16; off > 0; off >>= 1)
        m = fmaxf(m, __shfl_xor_sync(0xFFFFFFFFu, m, off));
    float s = expf(h.x - m) + expf(h.y - m);
#pragma unroll
    for (int off = 16; off > 0; off >>= 1)
        s += __shfl_xor_sync(0xFFFFFFFFu, s, off);
    float ls = logf(s);
    float2 r = make_float2(h.x - m - ls, h.y - m - ls);
    *reinterpret_cast<float2*>(&out[node * 64 + lane * 2]) = r;
}

// ---------------- pooling ----------------------------------------------------
__global__ void pool_kernel(const float* __restrict__ x, const int* __restrict__ gstart,
                            float* __restrict__ gout) {
    int warpsPerBlock = blockDim.x >> 5;
    int g = blockIdx.x * warpsPerBlock + (threadIdx.x >> 5);
    if (g >= N_GRAPHS) return;
    int lane = threadIdx.x & 31;
    int lo = gstart[g], hi = gstart[g + 1];
    float4 acc = make_float4(0.f, 0.f, 0.f, 0.f);
    for (int i = lo; i < hi; i++) {
        float4 v = *reinterpret_cast<const float4*>(&x[i * 128 + lane * 4]);
        acc.x += v.x; acc.y += v.y; acc.z += v.z; acc.w += v.w;
    }
    float inv = 1.f / (float)max(hi - lo, 1);
    acc.x *= inv; acc.y *= inv; acc.z *= inv; acc.w *= inv;
    *reinterpret_cast<float4*>(&gout[g * 128 + lane * 4]) = acc;
}

// ---------------- launch -----------------------------------------------------
extern "C" void kernel_launch(void* const* d_in, const int* in_sizes, int n_in,
                              void* d_out, int out_size) {
    const float* x       = (const float*)d_in[0];
    const int*   ei      = (const int*)d_in[1];
    const int*   cluster = (const int*)d_in[2];
    const float* Wl0 = (const float*)d_in[3];
    const float* bl0 = (const float*)d_in[4];
    const float* Wr0 = (const float*)d_in[5];
    const float* Wl1 = (const float*)d_in[6];
    const float* bl1 = (const float*)d_in[7];
    const float* Wr1 = (const float*)d_in[8];
    const float* Wl2 = (const float*)d_in[9];
    const float* bl2 = (const float*)d_in[10];
    const float* Wr2 = (const float*)d_in[11];

    const int* src = ei;
    const int* dst = ei + N_EDGES;

    float* out = (float*)d_out;
    float* out_lsm = out;
    float* out_pre = out + N_NODES * C_OUT;
    float* out_g   = out + N_NODES * C_OUT + N_NODES * C_HID;

    float *y, *z, *x2;
    uint32_t *ah, *al, *wh, *wl;
    int *deg, *fill, *ptr, *csrsrc, *gstart;
    cudaGetSymbolAddress((void**)&y, g_y);
    cudaGetSymbolAddress((void**)&z, g_z);
    cudaGetSymbolAddress((void**)&x2, g_x2);
    cudaGetSymbolAddress((void**)&ah, g_ah);
    cudaGetSymbolAddress((void**)&al, g_al);
    cudaGetSymbolAddress((void**)&wh, g_wh);
    cudaGetSymbolAddress((void**)&wl, g_wl);
    cudaGetSymbolAddress((void**)&deg, g_deg);
    cudaGetSymbolAddress((void**)&fill, g_fill);
    cudaGetSymbolAddress((void**)&ptr, g_ptr);
    cudaGetSymbolAddress((void**)&csrsrc, g_csrsrc);
    cudaGetSymbolAddress((void**)&gstart, g_gstart);

    const int SMEM128 = 2 * (16384 + 16384);  // 65536
    cudaFuncSetAttribute(bf16_gemm, cudaFuncAttributeMaxDynamicSharedMemorySize, SMEM128);

    // ---- fork: CSR build on side stream, packing+GEMM0 on main stream ----
    cudaStream_t sb;
    cudaStreamCreateWithFlags(&sb, cudaStreamNonBlocking);
    cudaEvent_t eFork, eJoin;
    cudaEventCreateWithFlags(&eFork, cudaEventDisableTiming);
    cudaEventCreateWithFlags(&eJoin, cudaEventDisableTiming);

    cudaEventRecord(eFork, 0);
    cudaStreamWaitEvent(sb, eFork, 0);
    cudaMemsetAsync(deg, 0, N_NODES * sizeof(int), sb);
    cudaMemsetAsync(fill, 0, N_NODES * sizeof(int), sb);
    const int EDGE_GRID = (N_EDGES + 255) / 256;  // 2344
    hist_gstart_kernel<<<EDGE_GRID, 256, 0, sb>>>(dst, deg, cluster, gstart);
    scan_kernel<<<1, 1024, 0, sb>>>(deg, ptr);
    fill_kernel<<<EDGE_GRID, 256, 0, sb>>>(src, dst, ptr, fill, csrsrc);
    cudaEventRecord(eJoin, sb);

    // main stream: pack + layer0 GEMM (independent of CSR)
    pack_w6<<<dim3(16, 6), 256>>>(Wl0, Wr0, Wl1, Wr1, Wl2, Wr2, wh, wl);
    pack_a<<<MT_PAD, 256>>>(x, ah, al, N_NODES);

    const int GEMM_GRID = 391;
    const int AGG_BLOCKS = (N_NODES + 7) / 8;
    dim3 gg(GEMM_GRID, 2);

    bf16_gemm<<<gg, 256, SMEM128>>>(ah, al,
        wh + 0 * 8192, wl + 0 * 8192, wh + 1 * 8192, wl + 1 * 8192, y, z, N_NODES);

    // join: aggregation needs the CSR
    cudaStreamWaitEvent(0, eJoin, 0);

    // ---- layer 0 aggregation (packed-only output) ----
    agg128_pack_kernel<<<AGG_BLOCKS, 256>>>(y, z, bl0, ptr, csrsrc, ah, al,
                                            nullptr, nullptr);

    // ---- layer 1 ----
    bf16_gemm<<<gg, 256, SMEM128>>>(ah, al,
        wh + 2 * 8192, wl + 2 * 8192, wh + 3 * 8192, wl + 3 * 8192, y, z, N_NODES);
    agg128_pack_kernel<<<AGG_BLOCKS, 256>>>(y, z, bl1, ptr, csrsrc, ah, al,
                                            out_pre, x2);

    // ---- pooling ----
    pool_kernel<<<(N_GRAPHS + 7) / 8, 256>>>(x2, gstart, out_g);

    // ---- layer 2: single fused GEMM ([Wl2|Wr2]) + log_softmax agg ----
    dim3 gg1(GEMM_GRID, 1);
    bf16_gemm<<<gg1, 256, SMEM128>>>(ah, al,
        wh + 4 * 8192, wl + 4 * 8192, wh + 4 * 8192, wl + 4 * 8192, y, y, N_NODES);
    agg64_lsm_kernel<<<AGG_BLOCKS, 256>>>(y, bl2, ptr, csrsrc, out_lsm);
}

// round 7
// speedup vs baseline: 1.7104x; 1.0284x over previous
#include <cuda_runtime.h>
#include <cuda_bf16.h>
#include <cuda_fp16.h>
#include <math.h>
#include <stdint.h>

#define N_NODES 50000
#define N_EDGES 600000
#define C_HID 128
#define C_OUT 64
#define N_GRAPHS 512
#define MT_PAD 3128   // 391*8 m-tiles of 16 rows (>= ceil(50000/16)=3125)

// ---------------- scratch (__device__ globals) -------------------------------
__device__ __half   g_yh[N_NODES * C_HID];    // y (gathered operand) in fp16
__device__ float    g_z[N_NODES * C_HID];     // z (self term) fp32
__device__ float    g_x2[N_NODES * C_HID];
__device__ uint32_t g_ah[MT_PAD * 8 * 128];   // A hi, fragment-packed bf16x2
__device__ uint32_t g_al[MT_PAD * 8 * 128];   // A lo
__device__ uint32_t g_wh[5 * 8192];           // weights hi (mat4 = [Wl2|Wr2] fused)
__device__ uint32_t g_wl[5 * 8192];           // weights lo
__device__ int      g_deg[N_NODES];
__device__ int      g_fill[N_NODES];
__device__ int      g_ptr[N_NODES + 1];
__device__ int      g_csrsrc[N_EDGES];
__device__ int      g_gstart[N_GRAPHS + 1];

// ---------------- CSR helpers -------------------------------------------------
__global__ void hist_gstart_kernel(const int* __restrict__ dst, int* __restrict__ deg,
                                   const int* __restrict__ cluster, int* __restrict__ gstart) {
    int i = blockIdx.x * blockDim.x + threadIdx.x;
    if (i < N_EDGES) atomicAdd(&deg[dst[i]], 1);
    if (i <= N_GRAPHS) {
        if (i == N_GRAPHS) gstart[i] = N_NODES;
        else {
            int lo = 0, hi = N_NODES;
            while (lo < hi) {
                int mid = (lo + hi) >> 1;
                if (cluster[mid] < i) lo = mid + 1; else hi = mid;
            }
            gstart[i] = lo;
        }
    }
}

__global__ void scan_kernel(const int* __restrict__ deg, int* __restrict__ ptr) {
    __shared__ int sums[1024];
    const int CHUNK = 49;
    int t = threadIdx.x;
    int base = t * CHUNK;
    int s = 0;
    for (int j = 0; j < CHUNK; j++) {
        int i = base + j;
        if (i < N_NODES) s += deg[i];
    }
    sums[t] = s;
    __syncthreads();
    for (int off = 1; off < 1024; off <<= 1) {
        int v = (t >= off) ? sums[t - off] : 0;
        __syncthreads();
        sums[t] += v;
        __syncthreads();
    }
    int run = (t == 0) ? 0 : sums[t - 1];
    for (int j = 0; j < CHUNK; j++) {
        int i = base + j;
        if (i < N_NODES) { ptr[i] = run; run += deg[i]; }
    }
    if (t == 0) ptr[N_NODES] = N_EDGES;
}

__global__ void fill_kernel(const int* __restrict__ src, const int* __restrict__ dst,
                            const int* __restrict__ ptr, int* __restrict__ fill,
                            int* __restrict__ csrsrc) {
    int i = blockIdx.x * blockDim.x + threadIdx.x;
    if (i >= N_EDGES) return;
    int d = dst[i];
    int pos = ptr[d] + atomicAdd(&fill[d], 1);
    csrsrc[pos] = src[i];
}

// ---------------- bf16 split/pack helpers ------------------------------------
__device__ __forceinline__ uint32_t pack_split(float x, float y, uint32_t& lo) {
    __nv_bfloat16 hx = __float2bfloat16(x);
    __nv_bfloat16 hy = __float2bfloat16(y);
    float rx = x - __bfloat162float(hx);
    float ry = y - __bfloat162float(hy);
    __nv_bfloat16 lx = __float2bfloat16(rx);
    __nv_bfloat16 ly = __float2bfloat16(ry);
    uint16_t bhx = *reinterpret_cast<uint16_t*>(&hx);
    uint16_t bhy = *reinterpret_cast<uint16_t*>(&hy);
    uint16_t blx = *reinterpret_cast<uint16_t*>(&lx);
    uint16_t bly = *reinterpret_cast<uint16_t*>(&ly);
    lo = ((uint32_t)bly << 16) | blx;
    return ((uint32_t)bhy << 16) | bhx;
}

// ---- pack A [M,128] f32 -> fragment-packed hi/lo bf16x2 tiles (layer0 only) --
__global__ void pack_a(const float* __restrict__ A, uint32_t* __restrict__ Ah,
                       uint32_t* __restrict__ Al, int M) {
    int tile = blockIdx.x * 8 + (threadIdx.x >> 5);
    if (tile >= MT_PAD * 8) return;
    int mt = tile >> 3, kt = tile & 7;
    int lane = threadIdx.x & 31, gid = lane >> 2, tig = lane & 3;
    uint32_t h[4], l[4];
#pragma unroll
    for (int r = 0; r < 4; r++) {
        int row = mt * 16 + gid + (r & 1) * 8;
        int col = kt * 16 + tig * 2 + (r >> 1) * 8;
        float2 v = make_float2(0.f, 0.f);
        if (row < M) v = *reinterpret_cast<const float2*>(&A[row * 128 + col]);
        h[r] = pack_split(v.x, v.y, l[r]);
    }
    *reinterpret_cast<uint4*>(&Ah[(tile * 32 + lane) * 4]) = make_uint4(h[0], h[1], h[2], h[3]);
    *reinterpret_cast<uint4*>(&Al[(tile * 32 + lane) * 4]) = make_uint4(l[0], l[1], l[2], l[3]);
}

// ---- pack weights: mats 0-3 = 128-wide; mats 4,5 (64-wide) fuse into slot 4 --
__global__ void pack_w6(const float* W0, const float* W1, const float* W2,
                        const float* W3, const float* W4, const float* W5,
                        uint32_t* __restrict__ Wh, uint32_t* __restrict__ Wl) {
    int mat = blockIdx.y;
    const float* W;
    int BNs, dst_mat, nt_off;
    switch (mat) {
        case 0: W = W0; BNs = 128; dst_mat = 0; nt_off = 0; break;
        case 1: W = W1; BNs = 128; dst_mat = 1; nt_off = 0; break;
        case 2: W = W2; BNs = 128; dst_mat = 2; nt_off = 0; break;
        case 3: W = W3; BNs = 128; dst_mat = 3; nt_off = 0; break;
        case 4: W = W4; BNs = 64;  dst_mat = 4; nt_off = 0; break;
        default: W = W5; BNs = 64; dst_mat = 4; nt_off = 8; break;
    }
    int NTs = BNs / 8;
    int tile = blockIdx.x * 8 + (threadIdx.x >> 5);
    if (tile >= 8 * NTs) return;
    int kt = tile / NTs, nt = tile % NTs;
    int lane = threadIdx.x & 31, gid = lane >> 2, tig = lane & 3;
    int col = nt * 8 + gid;
    uint32_t h[2], l[2];
#pragma unroll
    for (int r = 0; r < 2; r++) {
        int k = kt * 16 + tig * 2 + r * 8;
        float v0 = W[k * BNs + col];
        float v1 = W[(k + 1) * BNs + col];
        h[r] = pack_split(v0, v1, l[r]);
    }
    int didx = dst_mat * 8192 + (kt * 16 + nt + nt_off) * 64 + lane * 2;
    *reinterpret_cast<uint2*>(&Wh[didx]) = make_uint2(h[0], h[1]);
    *reinterpret_cast<uint2*>(&Wl[didx]) = make_uint2(l[0], l[1]);
}

// ---------------- bf16 split GEMM --------------------------------------------
__device__ __forceinline__ uint32_t smem_u32(const void* p) {
    uint32_t a;
    asm("{ .reg .u64 t; cvta.to.shared.u64 t, %1; cvt.u32.u64 %0, t; }" : "=r"(a) : "l"(p));
    return a;
}

__device__ __forceinline__ void cp16(uint32_t dst, const void* src) {
    asm volatile("cp.async.cg.shared.global [%0], [%1], 16;" :: "r"(dst), "l"(src) : "memory");
}

#define MMA_BF16(c, a, b)                                                         \
    asm volatile(                                                                 \
        "mma.sync.aligned.m16n8k16.row.col.f32.bf16.bf16.f32 "                    \
        "{%0,%1,%2,%3},{%4,%5,%6,%7},{%8,%9},{%0,%1,%2,%3};"                      \
        : "+f"(c[0]), "+f"(c[1]), "+f"(c[2]), "+f"(c[3])                          \
        : "r"(a[0]), "r"(a[1]), "r"(a[2]), "r"(a[3]), "r"(b[0]), "r"(b[1]))

// C = A[M,128] @ W[128,128]; blockIdx.y==0 -> fp16 store to C0h; ==1 -> f32 C1.
__global__ __launch_bounds__(256, 2) void bf16_gemm(
    const uint32_t* __restrict__ Ah, const uint32_t* __restrict__ Al,
    const uint32_t* __restrict__ Bh0, const uint32_t* __restrict__ Bl0,
    const uint32_t* __restrict__ Bh1, const uint32_t* __restrict__ Bl1,
    __half* __restrict__ C0h, float* __restrict__ C1, int M) {
    constexpr int NT = 16;
    constexpr int WNT = 4;
    constexpr int STAGE = 16384 + NT * 1024;
    extern __shared__ char smem[];

    const uint32_t* Bh = blockIdx.y ? Bh1 : Bh0;
    const uint32_t* Bl = blockIdx.y ? Bl1 : Bl0;

    uint32_t sb = smem_u32(smem);
    int tid = threadIdx.x, lane = tid & 31, warp = tid >> 5;
    int wm = warp & 1, wn = warp >> 1;
    int bRow = blockIdx.x * 128;

    float acc[4][WNT][4];
#pragma unroll
    for (int mt = 0; mt < 4; mt++)
#pragma unroll
        for (int nt = 0; nt < WNT; nt++)
#pragma unroll
            for (int j = 0; j < 4; j++) acc[mt][nt][j] = 0.f;

    auto load_stage = [&](int kc, int buf) {
#pragma unroll
        for (int i = 0; i < 4; i++) {                 // A: 16KB
            int c = tid + i * 256;
            int t = c >> 5, o = (c & 31) * 16;
            int pl = t >> 4, kt = (t >> 3) & 1, mt = t & 7;
            const uint32_t* src = (pl ? Al : Ah) +
                ((blockIdx.x * 8 + mt) * 8 + kc * 2 + kt) * 128;
            cp16(sb + buf * STAGE + t * 512 + o, (const char*)src + o);
        }
#pragma unroll
        for (int i = 0; i < NT / 4; i++) {            // B: 16KB
            int c = tid + i * 256;
            int t = c >> 4, o = (c & 15) * 16;
            int pl = t / (2 * NT);
            int kt = (t / NT) & 1;
            int nt = t % NT;
            const uint32_t* src = (pl ? Bl : Bh) + ((kc * 2 + kt) * NT + nt) * 64;
            cp16(sb + buf * STAGE + 16384 + t * 256 + o, (const char*)src + o);
        }
        asm volatile("cp.async.commit_group;" ::: "memory");
    };

    auto compute = [&](int buf) {
#pragma unroll
        for (int kt = 0; kt < 2; kt++) {
            uint32_t a[2][4][4];
#pragma unroll
            for (int pl = 0; pl < 2; pl++)
#pragma unroll
                for (int mt = 0; mt < 4; mt++) {
                    uint32_t ad = sb + buf * STAGE +
                        (((pl * 2 + kt) * 8) + (wm * 4 + mt)) * 512 + lane * 16;
                    asm volatile("ld.shared.v4.b32 {%0,%1,%2,%3},[%4];"
                        : "=r"(a[pl][mt][0]), "=r"(a[pl][mt][1]),
                          "=r"(a[pl][mt][2]), "=r"(a[pl][mt][3]) : "r"(ad));
                }
            uint32_t b[2][WNT][2];
#pragma unroll
            for (int pl = 0; pl < 2; pl++)
#pragma unroll
                for (int nt = 0; nt < WNT; nt++) {
                    uint32_t ad = sb + buf * STAGE + 16384 +
                        ((pl * 2 + kt) * NT + wn * WNT + nt) * 256 + lane * 8;
                    asm volatile("ld.shared.v2.b32 {%0,%1},[%2];"
                        : "=r"(b[pl][nt][0]), "=r"(b[pl][nt][1]) : "r"(ad));
                }
#pragma unroll
            for (int mt = 0; mt < 4; mt++)
#pragma unroll
                for (int nt = 0; nt < WNT; nt++) {
                    MMA_BF16(acc[mt][nt], a[0][mt], b[0][nt]);  // hi*hi
                    MMA_BF16(acc[mt][nt], a[0][mt], b[1][nt]);  // hi*lo
                    MMA_BF16(acc[mt][nt], a[1][mt], b[0][nt]);  // lo*hi
                }
        }
    };

    load_stage(0, 0);
    for (int kc = 0; kc < 4; kc++) {
        if (kc < 3) {
            load_stage(kc + 1, (kc + 1) & 1);
            asm volatile("cp.async.wait_group 1;" ::: "memory");
        } else {
            asm volatile("cp.async.wait_group 0;" ::: "memory");
        }
        __syncthreads();
        compute(kc & 1);
        __syncthreads();
    }

    int gid = lane >> 2, tig = lane & 3;
#pragma unroll
    for (int mt = 0; mt < 4; mt++) {
        int row = bRow + wm * 64 + mt * 16 + gid;
#pragma unroll
        for (int nt = 0; nt < WNT; nt++) {
            int col = wn * (8 * WNT) + nt * 8 + tig * 2;
            if (blockIdx.y == 0) {
                if (row < M)
                    *reinterpret_cast<__half2*>(&C0h[row * 128 + col]) =
                        __floats2half2_rn(acc[mt][nt][0], acc[mt][nt][1]);
                if (row + 8 < M)
                    *reinterpret_cast<__half2*>(&C0h[(row + 8) * 128 + col]) =
                        __floats2half2_rn(acc[mt][nt][2], acc[mt][nt][3]);
            } else {
                if (row < M)
                    *reinterpret_cast<float2*>(&C1[row * 128 + col]) =
                        make_float2(acc[mt][nt][0], acc[mt][nt][1]);
                if (row + 8 < M)
                    *reinterpret_cast<float2*>(&C1[(row + 8) * 128 + col]) =
                        make_float2(acc[mt][nt][2], acc[mt][nt][3]);
            }
        }
    }
}

// ------- aggregation (fp16 gather) + fused fragment-packing ------------------
__global__ void agg128_pack_kernel(const __half* __restrict__ yh, const float* __restrict__ z,
                                   const float* __restrict__ bl,
                                   const int* __restrict__ ptr, const int* __restrict__ csrsrc,
                                   uint32_t* __restrict__ Ah, uint32_t* __restrict__ Al,
                                   float* __restrict__ out_pre,
                                   float* __restrict__ out_f32) {
    int warpsPerBlock = blockDim.x >> 5;
    int node = blockIdx.x * warpsPerBlock + (threadIdx.x >> 5);
    if (node >= N_NODES) return;
    int lane = threadIdx.x & 31;

    int lo = ptr[node], hi = ptr[node + 1];
    float4 acc = make_float4(0.f, 0.f, 0.f, 0.f);
#pragma unroll 8
    for (int e = lo; e < hi; e++) {
        int s = csrsrc[e];
        uint2 raw = *reinterpret_cast<const uint2*>(&yh[s * 128 + lane * 4]);
        __half2 p0 = *reinterpret_cast<__half2*>(&raw.x);
        __half2 p1 = *reinterpret_cast<__half2*>(&raw.y);
        float2 f0 = __half22float2(p0);
        float2 f1 = __half22float2(p1);
        acc.x += f0.x; acc.y += f0.y; acc.z += f1.x; acc.w += f1.y;
    }
    float inv = 1.f / (float)max(hi - lo, 1);
    float4 b = *reinterpret_cast<const float4*>(&bl[lane * 4]);
    float4 zi = *reinterpret_cast<const float4*>(&z[node * 128 + lane * 4]);
    float4 h;
    h.x = acc.x * inv + b.x + zi.x;
    h.y = acc.y * inv + b.y + zi.y;
    h.z = acc.z * inv + b.z + zi.z;
    h.w = acc.w * inv + b.w + zi.w;
    if (out_pre) *reinterpret_cast<float4*>(&out_pre[node * 128 + lane * 4]) = h;
    float4 r = make_float4(fmaxf(h.x, 0.f), fmaxf(h.y, 0.f), fmaxf(h.z, 0.f), fmaxf(h.w, 0.f));
    if (out_f32) *reinterpret_cast<float4*>(&out_f32[node * 128 + lane * 4]) = r;

    int mt = node >> 4, gid = node & 7, rowhalf = (node >> 3) & 1;
    int kt = lane >> 2;
    float v01[2] = {r.x, r.z};
    float v11[2] = {r.y, r.w};
#pragma unroll
    for (int p = 0; p < 2; p++) {
        int c = lane * 4 + 2 * p;
        int ct = c & 15;
        int tig = (ct & 7) >> 1;
        int colhalf = ct >> 3;
        int reg = rowhalf + 2 * colhalf;
        int idx = ((mt * 8 + kt) * 32 + gid * 4 + tig) * 4 + reg;
        uint32_t lo32;
        uint32_t hi32 = pack_split(v01[p], v11[p], lo32);
        Ah[idx] = hi32;
        Al[idx] = lo32;
    }
}

// ------- final aggregation (64-ch, interleaved fp16 y|z) + log_softmax -------
__global__ void agg64_lsm_kernel(const __half* __restrict__ yzh,
                                 const float* __restrict__ bl,
                                 const int* __restrict__ ptr, const int* __restrict__ csrsrc,
                                 float* __restrict__ out) {
    int warpsPerBlock = blockDim.x >> 5;
    int node = blockIdx.x * warpsPerBlock + (threadIdx.x >> 5);
    if (node >= N_NODES) return;
    int lane = threadIdx.x & 31;

    int lo = ptr[node], hi = ptr[node + 1];
    float2 acc = make_float2(0.f, 0.f);
#pragma unroll 8
    for (int e = lo; e < hi; e++) {
        int s = csrsrc[e];
        __half2 v = *reinterpret_cast<const __half2*>(&yzh[s * 128 + lane * 2]);
        float2 f = __half22float2(v);
        acc.x += f.x; acc.y += f.y;
    }
    float inv = 1.f / (float)max(hi - lo, 1);
    float2 b = *reinterpret_cast<const float2*>(&bl[lane * 2]);
    __half2 zv = *reinterpret_cast<const __half2*>(&yzh[node * 128 + 64 + lane * 2]);
    float2 zi = __half22float2(zv);
    float2 h;
    h.x = acc.x * inv + b.x + zi.x;
    h.y = acc.y * inv + b.y + zi.y;

    float m = fmaxf(h.x, h.y);
#pragma unroll
    for (int off = 16; off > 0; off >>= 1)
        m = fmaxf(m, __shfl_xor_sync(0xFFFFFFFFu, m, off));
    float s = expf(h.x - m) + expf(h.y - m);
#pragma unroll
    for (int off = 16; off > 0; off >>= 1)
        s += __shfl_xor_sync(0xFFFFFFFFu, s, off);
    float ls = logf(s);
    float2 r = make_float2(h.x - m - ls, h.y - m - ls);
    *reinterpret_cast<float2*>(&out[node * 64 + lane * 2]) = r;
}

// ---------------- pooling ----------------------------------------------------
__global__ void pool_kernel(const float* __restrict__ x, const int* __restrict__ gstart,
                            float* __restrict__ gout) {
    int warpsPerBlock = blockDim.x >> 5;
    int g = blockIdx.x * warpsPerBlock + (threadIdx.x >> 5);
    if (g >= N_GRAPHS) return;
    int lane = threadIdx.x & 31;
    int lo = gstart[g], hi = gstart[g + 1];
    float4 acc = make_float4(0.f, 0.f, 0.f, 0.f);
    for (int i = lo; i < hi; i++) {
        float4 v = *reinterpret_cast<const float4*>(&x[i * 128 + lane * 4]);
        acc.x += v.x; acc.y += v.y; acc.z += v.z; acc.w += v.w;
    }
    float inv = 1.f / (float)max(hi - lo, 1);
    acc.x *= inv; acc.y *= inv; acc.z *= inv; acc.w *= inv;
    *reinterpret_cast<float4*>(&gout[g * 128 + lane * 4]) = acc;
}

// ---------------- launch -----------------------------------------------------
extern "C" void kernel_launch(void* const* d_in, const int* in_sizes, int n_in,
                              void* d_out, int out_size) {
    const float* x       = (const float*)d_in[0];
    const int*   ei      = (const int*)d_in[1];
    const int*   cluster = (const int*)d_in[2];
    const float* Wl0 = (const float*)d_in[3];
    const float* bl0 = (const float*)d_in[4];
    const float* Wr0 = (const float*)d_in[5];
    const float* Wl1 = (const float*)d_in[6];
    const float* bl1 = (const float*)d_in[7];
    const float* Wr1 = (const float*)d_in[8];
    const float* Wl2 = (const float*)d_in[9];
    const float* bl2 = (const float*)d_in[10];
    const float* Wr2 = (const float*)d_in[11];

    const int* src = ei;
    const int* dst = ei + N_EDGES;

    float* out = (float*)d_out;
    float* out_lsm = out;
    float* out_pre = out + N_NODES * C_OUT;
    float* out_g   = out + N_NODES * C_OUT + N_NODES * C_HID;

    __half* yh;
    float *z, *x2;
    uint32_t *ah, *al, *wh, *wl;
    int *deg, *fill, *ptr, *csrsrc, *gstart;
    cudaGetSymbolAddress((void**)&yh, g_yh);
    cudaGetSymbolAddress((void**)&z, g_z);
    cudaGetSymbolAddress((void**)&x2, g_x2);
    cudaGetSymbolAddress((void**)&ah, g_ah);
    cudaGetSymbolAddress((void**)&al, g_al);
    cudaGetSymbolAddress((void**)&wh, g_wh);
    cudaGetSymbolAddress((void**)&wl, g_wl);
    cudaGetSymbolAddress((void**)&deg, g_deg);
    cudaGetSymbolAddress((void**)&fill, g_fill);
    cudaGetSymbolAddress((void**)&ptr, g_ptr);
    cudaGetSymbolAddress((void**)&csrsrc, g_csrsrc);
    cudaGetSymbolAddress((void**)&gstart, g_gstart);

    const int SMEM128 = 2 * (16384 + 16384);  // 65536
    cudaFuncSetAttribute(bf16_gemm, cudaFuncAttributeMaxDynamicSharedMemorySize, SMEM128);

    // ---- fork: CSR build on side stream ----
    cudaStream_t sb;
    cudaStreamCreateWithFlags(&sb, cudaStreamNonBlocking);
    cudaEvent_t eFork, eJoin;
    cudaEventCreateWithFlags(&eFork, cudaEventDisableTiming);
    cudaEventCreateWithFlags(&eJoin, cudaEventDisableTiming);

    cudaEventRecord(eFork, 0);
    cudaStreamWaitEvent(sb, eFork, 0);
    cudaMemsetAsync(deg, 0, N_NODES * sizeof(int), sb);
    cudaMemsetAsync(fill, 0, N_NODES * sizeof(int), sb);
    const int EDGE_GRID = (N_EDGES + 255) / 256;  // 2344
    hist_gstart_kernel<<<EDGE_GRID, 256, 0, sb>>>(dst, deg, cluster, gstart);
    scan_kernel<<<1, 1024, 0, sb>>>(deg, ptr);
    fill_kernel<<<EDGE_GRID, 256, 0, sb>>>(src, dst, ptr, fill, csrsrc);
    cudaEventRecord(eJoin, sb);

    // main stream: pack + layer0 GEMM (independent of CSR)
    pack_w6<<<dim3(16, 6), 256>>>(Wl0, Wr0, Wl1, Wr1, Wl2, Wr2, wh, wl);
    pack_a<<<MT_PAD, 256>>>(x, ah, al, N_NODES);

    const int GEMM_GRID = 391;
    const int AGG_BLOCKS = (N_NODES + 7) / 8;
    dim3 gg(GEMM_GRID, 2);

    bf16_gemm<<<gg, 256, SMEM128>>>(ah, al,
        wh + 0 * 8192, wl + 0 * 8192, wh + 1 * 8192, wl + 1 * 8192, yh, z, N_NODES);

    cudaStreamWaitEvent(0, eJoin, 0);

    // ---- layer 0 aggregation (packed-only output) ----
    agg128_pack_kernel<<<AGG_BLOCKS, 256>>>(yh, z, bl0, ptr, csrsrc, ah, al,
                                            nullptr, nullptr);

    // ---- layer 1 ----
    bf16_gemm<<<gg, 256, SMEM128>>>(ah, al,
        wh + 2 * 8192, wl + 2 * 8192, wh + 3 * 8192, wl + 3 * 8192, yh, z, N_NODES);
    agg128_pack_kernel<<<AGG_BLOCKS, 256>>>(yh, z, bl1, ptr, csrsrc, ah, al,
                                            out_pre, x2);

    // ---- pooling ----
    pool_kernel<<<(N_GRAPHS + 7) / 8, 256>>>(x2, gstart, out_g);

    // ---- layer 2: single fused GEMM ([Wl2|Wr2], all-fp16 row) + lsm agg ----
    dim3 gg1(GEMM_GRID, 1);
    bf16_gemm<<<gg1, 256, SMEM128>>>(ah, al,
        wh + 4 * 8192, wl + 4 * 8192, wh + 4 * 8192, wl + 4 * 8192, yh, nullptr, N_NODES);
    agg64_lsm_kernel<<<AGG_BLOCKS, 256>>>(yh, bl2, ptr, csrsrc, out_lsm);
}